// round 1
// baseline (speedup 1.0000x reference)
#include <cuda_runtime.h>
#include <math.h>
#include <stdint.h>

#define Bb 8
#define HH 32
#define WW 32
#define E 256
#define HEADS 8
#define KD 32
#define FFN 1024
#define NQ 64
#define L 1024
#define SCALING 0.17677669529663687f

// ---------------- scratch arena (no allocations allowed) ----------------
#define SZ_TOK (Bb * L * E)        // 2,097,152
#define SZ_QTK (Bb * NQ * E)       // 131,072
#define OFF_X1   ((size_t)0)
#define OFF_HN   (OFF_X1   + SZ_TOK)
#define OFF_Q    (OFF_HN   + SZ_TOK)
#define OFF_K    (OFF_Q    + SZ_TOK)
#define OFF_V    (OFF_K    + SZ_TOK)
#define OFF_LEPE (OFF_V    + SZ_TOK)
#define OFF_AO   (OFF_LEPE + SZ_TOK)
#define OFF_X2   (OFF_AO   + SZ_TOK)
#define OFF_FF   (OFF_X2   + SZ_TOK)
#define OFF_CK   (OFF_FF   + (size_t)Bb * L * FFN)
#define OFF_CV   (OFF_CK   + SZ_TOK)
#define OFF_CQ   (OFF_CV   + SZ_TOK)
#define OFF_CAO  (OFF_CQ   + SZ_QTK)
#define OFF_Q2   (OFF_CAO  + SZ_QTK)
#define OFF_QLN  (OFF_Q2   + SZ_QTK)
#define OFF_QLN2 (OFF_QLN  + SZ_QTK)
#define OFF_QFF  (OFF_QLN2 + SZ_QTK)
#define SCRATCH_TOTAL (OFF_QFF + (size_t)Bb * NQ * FFN)

__device__ float g_scratch[SCRATCH_TOTAL];

// ---------------- depthwise conv (3x3 or 5x5), NHWC, 256 ch/block -------
template <int KS, bool ADDIN>
__global__ void dwconv_kernel(const float* __restrict__ in,
                              const float* __restrict__ w,
                              const float* __restrict__ bias,
                              float* __restrict__ out) {
    const int P = KS / 2;
    int c = threadIdx.x;
    int wx = blockIdx.x, hy = blockIdx.y, b = blockIdx.z;
    float acc = bias[c];
#pragma unroll
    for (int kh = 0; kh < KS; kh++) {
        int y = hy + kh - P;
        if (y < 0 || y >= HH) continue;
#pragma unroll
        for (int kw = 0; kw < KS; kw++) {
            int xx = wx + kw - P;
            if (xx < 0 || xx >= WW) continue;
            acc += in[(((size_t)b * HH + y) * WW + xx) * E + c] *
                   w[c * KS * KS + kh * KS + kw];
        }
    }
    size_t o = (((size_t)b * HH + hy) * WW + wx) * E + c;
    out[o] = ADDIN ? (in[o] + acc) : acc;
}

// ---------------- layernorm over E=256, one row per block ---------------
__global__ void ln_kernel(const float* __restrict__ in,
                          const float* __restrict__ g,
                          const float* __restrict__ b,
                          float* __restrict__ out) {
    int row = blockIdx.x;
    int t = threadIdx.x;
    float v = in[(size_t)row * E + t];
    __shared__ float s1[256], s2[256];
    s1[t] = v; s2[t] = v * v;
    __syncthreads();
    for (int o = 128; o > 0; o >>= 1) {
        if (t < o) { s1[t] += s1[t + o]; s2[t] += s2[t + o]; }
        __syncthreads();
    }
    float m = s1[0] * (1.0f / E);
    float var = s2[0] * (1.0f / E) - m * m;
    float inv = rsqrtf(var + 1e-6f);
    out[(size_t)row * E + t] = (v - m) * inv * g[t] + b[t];
}

// ---------------- theta shift on Q and K (in place) ---------------------
__global__ void theta_kernel(float* __restrict__ q, float* __restrict__ k,
                             const float* __restrict__ sn,
                             const float* __restrict__ cs) {
    int idx = blockIdx.x * blockDim.x + threadIdx.x;   // pair index
    if (idx >= Bb * L * (E / 2)) return;
    int e0 = (idx % (E / 2)) * 2;
    int bl = idx / (E / 2);
    int l = bl % L;
    int dd0 = e0 & 31;
    int sidx = l * KD + dd0;
    float s0 = sn[sidx], c0 = cs[sidx], s1 = sn[sidx + 1], c1 = cs[sidx + 1];
    size_t base = (size_t)bl * E + e0;
    float q0 = q[base], q1 = q[base + 1];
    q[base]     = q0 * c0 - q1 * s0;
    q[base + 1] = q1 * c1 + q0 * s1;
    float k0 = k[base], k1 = k[base + 1];
    k[base]     = k0 * c0 - k1 * s0;
    k[base + 1] = k1 * c1 + k0 * s1;
}

// ---------------- generic SGEMM: C = epi( (A[+A2]) @ W^T ) -------------
// A: [M,K] row-major, W: [N,K] row-major, out = alpha*(acc + bias[n]),
// optional exact GELU, optional residual add. M,N % 64 == 0, K % 16 == 0.
__global__ void sgemm_kernel(const float* __restrict__ A,
                             const float* __restrict__ A2,
                             const float* __restrict__ W,
                             const float* __restrict__ bias,
                             const float* __restrict__ res,
                             float* __restrict__ C,
                             int M, int N, int K, float alpha, int gelu_flag) {
    __shared__ float As[16][64];
    __shared__ float Bs[16][64];
    int tid = threadIdx.x;
    int tx = tid & 15, ty = tid >> 4;
    int n0 = blockIdx.x * 64, m0 = blockIdx.y * 64;
    int lr = tid >> 2;          // 0..63
    int lc = (tid & 3) * 4;     // 0,4,8,12
    float acc[4][4] = {};
    for (int k0 = 0; k0 < K; k0 += 16) {
        float4 av = *(const float4*)&A[(size_t)(m0 + lr) * K + k0 + lc];
        if (A2) {
            float4 a2 = *(const float4*)&A2[(size_t)(m0 + lr) * K + k0 + lc];
            av.x += a2.x; av.y += a2.y; av.z += a2.z; av.w += a2.w;
        }
        float4 bv = *(const float4*)&W[(size_t)(n0 + lr) * K + k0 + lc];
        As[lc + 0][lr] = av.x; As[lc + 1][lr] = av.y;
        As[lc + 2][lr] = av.z; As[lc + 3][lr] = av.w;
        Bs[lc + 0][lr] = bv.x; Bs[lc + 1][lr] = bv.y;
        Bs[lc + 2][lr] = bv.z; Bs[lc + 3][lr] = bv.w;
        __syncthreads();
#pragma unroll
        for (int k = 0; k < 16; k++) {
            float4 a = *(const float4*)&As[k][ty * 4];
            float4 b = *(const float4*)&Bs[k][tx * 4];
            float aa[4] = {a.x, a.y, a.z, a.w};
            float bb[4] = {b.x, b.y, b.z, b.w};
#pragma unroll
            for (int i = 0; i < 4; i++)
#pragma unroll
                for (int j = 0; j < 4; j++)
                    acc[i][j] += aa[i] * bb[j];
        }
        __syncthreads();
    }
#pragma unroll
    for (int i = 0; i < 4; i++) {
        int m = m0 + ty * 4 + i;
#pragma unroll
        for (int j = 0; j < 4; j++) {
            int n = n0 + tx * 4 + j;
            float v = (acc[i][j] + bias[n]) * alpha;
            if (gelu_flag) v = 0.5f * v * (1.0f + erff(v * 0.70710678118654752f));
            if (res) v += res[(size_t)m * N + n];
            C[(size_t)m * N + n] = v;
        }
    }
}

// ---------------- flash attention ---------------------------------------
// Q: [B, Lq, E] head-major cols, K/V: [B, Lk, E]. One warp per query row,
// 8 queries per block, 64-key chunks. mask (optional): [HEADS, Lk, Lk]
// indexed [h, qg, j]. O: [B, Lq, E].
__global__ void attn_kernel(const float* __restrict__ Q,
                            const float* __restrict__ Kt,
                            const float* __restrict__ V,
                            const float* __restrict__ mask,
                            float* __restrict__ O,
                            int Lq, int Lk, float scale) {
    __shared__ float Ks[64][33];
    __shared__ float Vs[64][33];
    __shared__ float ps[8][64];
    __shared__ float qs[8][32];
    int tid = threadIdx.x;
    int w = tid >> 5, lane = tid & 31;
    int h = blockIdx.y, b = blockIdx.z;
    int qg = blockIdx.x * 8 + w;
    qs[w][lane] = Q[((size_t)(b * Lq + qg)) * E + h * KD + lane];
    const float* mrow = mask ? (mask + ((size_t)h * Lk + qg) * Lk) : nullptr;
    float m = -INFINITY, lsum = 0.f, acc = 0.f;
    int r = tid >> 3;
    int c4 = (tid & 7) * 4;
    for (int j0 = 0; j0 < Lk; j0 += 64) {
        __syncthreads();
#pragma unroll
        for (int p = 0; p < 2; p++) {
            int row = p * 32 + r;
            size_t gidx = ((size_t)(b * Lk + j0 + row)) * E + h * KD + c4;
            float4 kv = *(const float4*)&Kt[gidx];
            Ks[row][c4 + 0] = kv.x; Ks[row][c4 + 1] = kv.y;
            Ks[row][c4 + 2] = kv.z; Ks[row][c4 + 3] = kv.w;
            float4 vv = *(const float4*)&V[gidx];
            Vs[row][c4 + 0] = vv.x; Vs[row][c4 + 1] = vv.y;
            Vs[row][c4 + 2] = vv.z; Vs[row][c4 + 3] = vv.w;
        }
        __syncthreads();
        float s0 = 0.f, s1 = 0.f;
#pragma unroll
        for (int d = 0; d < 32; d++) {
            float qd = qs[w][d];
            s0 += qd * Ks[lane][d];
            s1 += qd * Ks[lane + 32][d];
        }
        s0 *= scale; s1 *= scale;
        if (mrow) { s0 += mrow[j0 + lane]; s1 += mrow[j0 + lane + 32]; }
        float cm = fmaxf(s0, s1);
#pragma unroll
        for (int o = 16; o > 0; o >>= 1)
            cm = fmaxf(cm, __shfl_xor_sync(0xffffffff, cm, o));
        float mn = fmaxf(m, cm);
        float al = expf(m - mn);
        float p0 = expf(s0 - mn), p1 = expf(s1 - mn);
        ps[w][lane] = p0; ps[w][lane + 32] = p1;
        float csum = p0 + p1;
#pragma unroll
        for (int o = 16; o > 0; o >>= 1)
            csum += __shfl_xor_sync(0xffffffff, csum, o);
        lsum = lsum * al + csum;
        acc *= al;
        __syncwarp();
#pragma unroll
        for (int j = 0; j < 64; j++)
            acc += ps[w][j] * Vs[j][lane];
        m = mn;
    }
    O[((size_t)(b * Lq + qg)) * E + h * KD + lane] = acc / lsum;
}

// ---------------- launcher ----------------------------------------------
extern "C" void kernel_launch(void* const* d_in, const int* in_sizes, int n_in,
                              void* d_out, int out_size) {
    const float* x       = (const float*)d_in[0];
    const float* queries = (const float*)d_in[1];
    const float* sn      = (const float*)d_in[2];
    const float* cs      = (const float*)d_in[3];
    const float* mask    = (const float*)d_in[4];
    const float* ln1_g   = (const float*)d_in[5];
    const float* ln1_b   = (const float*)d_in[6];
    const float* ln2_g   = (const float*)d_in[7];
    const float* ln2_b   = (const float*)d_in[8];
    const float* wq      = (const float*)d_in[9];
    const float* bq      = (const float*)d_in[10];
    const float* wk      = (const float*)d_in[11];
    const float* bk      = (const float*)d_in[12];
    const float* wv      = (const float*)d_in[13];
    const float* bv      = (const float*)d_in[14];
    const float* lepe_w  = (const float*)d_in[15];
    const float* lepe_b  = (const float*)d_in[16];
    const float* wo      = (const float*)d_in[17];
    const float* bo      = (const float*)d_in[18];
    const float* fc1_w   = (const float*)d_in[19];
    const float* fc1_b   = (const float*)d_in[20];
    const float* fc2_w   = (const float*)d_in[21];
    const float* fc2_b   = (const float*)d_in[22];
    const float* pos_w   = (const float*)d_in[23];
    const float* pos_b   = (const float*)d_in[24];
    const float* ca_in_w = (const float*)d_in[25];
    const float* ca_in_b = (const float*)d_in[26];
    const float* ca_out_w= (const float*)d_in[27];
    const float* ca_out_b= (const float*)d_in[28];

    void* sp = nullptr;
    cudaGetSymbolAddress(&sp, g_scratch);
    float* S = (float*)sp;
    float* X1   = S + OFF_X1;
    float* HN   = S + OFF_HN;
    float* Qb   = S + OFF_Q;
    float* Kb   = S + OFF_K;
    float* Vb   = S + OFF_V;
    float* LEPE = S + OFF_LEPE;
    float* AO   = S + OFF_AO;
    float* X2   = S + OFF_X2;
    float* FF   = S + OFF_FF;
    float* CK   = S + OFF_CK;
    float* CV   = S + OFF_CV;
    float* CQ   = S + OFF_CQ;
    float* CAO  = S + OFF_CAO;
    float* Q2   = S + OFF_Q2;
    float* QLN  = S + OFF_QLN;
    float* QLN2 = S + OFF_QLN2;
    float* QFF  = S + OFF_QFF;

    float* OX = (float*)d_out;            // x output: B*L*E
    float* OQ = OX + (size_t)Bb * L * E;  // queries output: B*NQ*E

    const int MTOK = Bb * L;   // 8192
    const int MQ   = Bb * NQ;  // 512
    dim3 sp3(WW, HH, Bb);

    // 1. x = x + dwconv3x3(x)
    dwconv_kernel<3, true><<<sp3, 256>>>(x, pos_w, pos_b, X1);
    // 2. hn = LN1(x)
    ln_kernel<<<MTOK, 256>>>(X1, ln1_g, ln1_b, HN);
    // 3. q, k (pre-scaled), v
    sgemm_kernel<<<dim3(E/64, MTOK/64), 256>>>(HN, nullptr, wq, bq, nullptr, Qb, MTOK, E, E, 1.f, 0);
    sgemm_kernel<<<dim3(E/64, MTOK/64), 256>>>(HN, nullptr, wk, bk, nullptr, Kb, MTOK, E, E, SCALING, 0);
    sgemm_kernel<<<dim3(E/64, MTOK/64), 256>>>(HN, nullptr, wv, bv, nullptr, Vb, MTOK, E, E, 1.f, 0);
    // 4. lepe = dwconv5x5(v)
    dwconv_kernel<5, false><<<sp3, 256>>>(Vb, lepe_w, lepe_b, LEPE);
    // 5. theta shift q, k
    theta_kernel<<<(Bb * L * (E/2) + 255) / 256, 256>>>(Qb, Kb, sn, cs);
    // 6. self attention (k pre-scaled, additive mask)
    attn_kernel<<<dim3(L/8, HEADS, Bb), 256>>>(Qb, Kb, Vb, mask, AO, L, L, 1.f);
    // 7. x = x + (attn_out + lepe) @ wo^T + bo
    sgemm_kernel<<<dim3(E/64, MTOK/64), 256>>>(AO, LEPE, wo, bo, X1, X2, MTOK, E, E, 1.f, 0);
    // 8. FFN on x
    ln_kernel<<<MTOK, 256>>>(X2, ln2_g, ln2_b, HN);
    sgemm_kernel<<<dim3(FFN/64, MTOK/64), 256>>>(HN, nullptr, fc1_w, fc1_b, nullptr, FF, MTOK, FFN, E, 1.f, 1);
    sgemm_kernel<<<dim3(E/64, MTOK/64), 256>>>(FF, nullptr, fc2_w, fc2_b, X2, OX, MTOK, E, FFN, 1.f, 0);
    // 9. cross attention: q from LN1(queries); k,v from xs = final x
    ln_kernel<<<MQ, 256>>>(queries, ln1_g, ln1_b, QLN);
    sgemm_kernel<<<dim3(E/64, MQ/64), 256>>>(QLN, nullptr, ca_in_w,           ca_in_b,       nullptr, CQ, MQ,   E, E, 1.f, 0);
    sgemm_kernel<<<dim3(E/64, MTOK/64), 256>>>(OX, nullptr, ca_in_w + E*E,    ca_in_b + E,   nullptr, CK, MTOK, E, E, 1.f, 0);
    sgemm_kernel<<<dim3(E/64, MTOK/64), 256>>>(OX, nullptr, ca_in_w + 2*E*E,  ca_in_b + 2*E, nullptr, CV, MTOK, E, E, 1.f, 0);
    attn_kernel<<<dim3(NQ/8, HEADS, Bb), 256>>>(CQ, CK, CV, nullptr, CAO, NQ, L, SCALING);
    sgemm_kernel<<<dim3(E/64, MQ/64), 256>>>(CAO, nullptr, ca_out_w, ca_out_b, queries, Q2, MQ, E, E, 1.f, 0);
    // 10. FFN on queries
    ln_kernel<<<MQ, 256>>>(Q2, ln2_g, ln2_b, QLN2);
    sgemm_kernel<<<dim3(FFN/64, MQ/64), 256>>>(QLN2, nullptr, fc1_w, fc1_b, nullptr, QFF, MQ, FFN, E, 1.f, 1);
    sgemm_kernel<<<dim3(E/64, MQ/64), 256>>>(QFF, nullptr, fc2_w, fc2_b, Q2, OQ, MQ, E, FFN, 1.f, 0);
}

// round 2
// speedup vs baseline: 1.3384x; 1.3384x over previous
#include <cuda_runtime.h>
#include <math.h>
#include <stdint.h>

#define Bb 8
#define HH 32
#define WW 32
#define E 256
#define HEADS 8
#define KD 32
#define FFN 1024
#define NQ 64
#define L 1024
#define SCALING 0.17677669529663687f

// ---------------- scratch arena (no allocations allowed) ----------------
#define SZ_TOK (Bb * L * E)        // 2,097,152
#define SZ_QTK (Bb * NQ * E)       // 131,072
#define OFF_X1   ((size_t)0)
#define OFF_HN   (OFF_X1   + SZ_TOK)
#define OFF_Q    (OFF_HN   + SZ_TOK)
#define OFF_K    (OFF_Q    + SZ_TOK)
#define OFF_V    (OFF_K    + SZ_TOK)
#define OFF_LEPE (OFF_V    + SZ_TOK)
#define OFF_AO   (OFF_LEPE + SZ_TOK)
#define OFF_X2   (OFF_AO   + SZ_TOK)
#define OFF_FF   (OFF_X2   + SZ_TOK)
#define OFF_CK   (OFF_FF   + (size_t)Bb * L * FFN)
#define OFF_CV   (OFF_CK   + SZ_TOK)
#define OFF_CQ   (OFF_CV   + SZ_TOK)
#define OFF_CAO  (OFF_CQ   + SZ_QTK)
#define OFF_Q2   (OFF_CAO  + SZ_QTK)
#define OFF_QLN  (OFF_Q2   + SZ_QTK)
#define OFF_QLN2 (OFF_QLN  + SZ_QTK)
#define OFF_QFF  (OFF_QLN2 + SZ_QTK)
#define SCRATCH_TOTAL (OFF_QFF + (size_t)Bb * NQ * FFN)

__device__ float g_scratch[SCRATCH_TOTAL];

// ---------------- depthwise conv (3x3 or 5x5), NHWC, 256 ch/block -------
template <int KS, bool ADDIN>
__global__ void dwconv_kernel(const float* __restrict__ in,
                              const float* __restrict__ w,
                              const float* __restrict__ bias,
                              float* __restrict__ out) {
    const int P = KS / 2;
    int c = threadIdx.x;
    int wx = blockIdx.x, hy = blockIdx.y, b = blockIdx.z;
    float acc = bias[c];
#pragma unroll
    for (int kh = 0; kh < KS; kh++) {
        int y = hy + kh - P;
        if (y < 0 || y >= HH) continue;
#pragma unroll
        for (int kw = 0; kw < KS; kw++) {
            int xx = wx + kw - P;
            if (xx < 0 || xx >= WW) continue;
            acc += in[(((size_t)b * HH + y) * WW + xx) * E + c] *
                   w[c * KS * KS + kh * KS + kw];
        }
    }
    size_t o = (((size_t)b * HH + hy) * WW + wx) * E + c;
    out[o] = ADDIN ? (in[o] + acc) : acc;
}

// ---------------- layernorm over E=256, one row per block ---------------
__global__ void ln_kernel(const float* __restrict__ in,
                          const float* __restrict__ g,
                          const float* __restrict__ b,
                          float* __restrict__ out) {
    int row = blockIdx.x;
    int t = threadIdx.x;
    float v = in[(size_t)row * E + t];
    __shared__ float s1[256], s2[256];
    s1[t] = v; s2[t] = v * v;
    __syncthreads();
    for (int o = 128; o > 0; o >>= 1) {
        if (t < o) { s1[t] += s1[t + o]; s2[t] += s2[t + o]; }
        __syncthreads();
    }
    float m = s1[0] * (1.0f / E);
    float var = s2[0] * (1.0f / E) - m * m;
    float inv = rsqrtf(var + 1e-6f);
    out[(size_t)row * E + t] = (v - m) * inv * g[t] + b[t];
}

// ---------------- theta shift on Q and K (in place) ---------------------
__global__ void theta_kernel(float* __restrict__ q, float* __restrict__ k,
                             const float* __restrict__ sn,
                             const float* __restrict__ cs) {
    int idx = blockIdx.x * blockDim.x + threadIdx.x;   // pair index
    if (idx >= Bb * L * (E / 2)) return;
    int e0 = (idx % (E / 2)) * 2;
    int bl = idx / (E / 2);
    int l = bl % L;
    int dd0 = e0 & 31;
    int sidx = l * KD + dd0;
    float s0 = sn[sidx], c0 = cs[sidx], s1 = sn[sidx + 1], c1 = cs[sidx + 1];
    size_t base = (size_t)bl * E + e0;
    float q0 = q[base], q1 = q[base + 1];
    q[base]     = q0 * c0 - q1 * s0;
    q[base + 1] = q1 * c1 + q0 * s1;
    float k0 = k[base], k1 = k[base + 1];
    k[base]     = k0 * c0 - k1 * s0;
    k[base + 1] = k1 * c1 + k0 * s1;
}

// ---------------- tf32 tensor-core GEMM ---------------------------------
// C[M,N] = epi( (A[+A2]) @ W^T ), A:[M,K] rm, W:[N,K] rm.
// Block tile 128x64, k-tile 32, 8 warps of 32x32 (2x4 m16n8k8 mma tiles).
// Swizzled smem: row = 32 floats, float4 slot f stored at f ^ (row & 7).
__device__ __forceinline__ uint32_t f2tf32(float x) {
    uint32_t r;
    asm("cvt.rna.tf32.f32 %0, %1;" : "=r"(r) : "f"(x));
    return r;
}

#define SWIDX(r, k) (((r) << 5) + (((((k) >> 2) ^ ((r) & 7))) << 2) + ((k) & 3))

__global__ void mma_gemm_kernel(const float* __restrict__ A,
                                const float* __restrict__ A2,
                                const float* __restrict__ W,
                                const float* __restrict__ bias,
                                const float* __restrict__ res,
                                float* __restrict__ C,
                                int M, int N, int K, float alpha, int gelu_flag) {
    __shared__ float As[128 * 32];
    __shared__ float Bs[64 * 32];
    int tid = threadIdx.x;
    int w = tid >> 5, lane = tid & 31;
    int wm = (w & 3) * 32, wn = (w >> 2) * 32;
    int m0 = blockIdx.y * 128, n0 = blockIdx.x * 64;
    int lm = tid >> 3;   // 0..31 (row within group of 32)
    int lf = tid & 7;    // 0..7  (float4 slot along k)
    int lg = lane >> 2;  // 0..7
    int lt = lane & 3;   // 0..3
    int sw = lf ^ (lm & 7);

    float acc[2][4][4] = {};

    for (int k0 = 0; k0 < K; k0 += 32) {
        // A tile: 128 x 32
#pragma unroll
        for (int i = 0; i < 4; i++) {
            int row = lm + 32 * i;
            size_t g = (size_t)(m0 + row) * K + k0 + lf * 4;
            float4 v = *(const float4*)&A[g];
            if (A2) {
                float4 u = *(const float4*)&A2[g];
                v.x += u.x; v.y += u.y; v.z += u.z; v.w += u.w;
            }
            uint4 t;
            t.x = f2tf32(v.x); t.y = f2tf32(v.y);
            t.z = f2tf32(v.z); t.w = f2tf32(v.w);
            *(uint4*)&As[row * 32 + sw * 4] = t;
        }
        // B tile: 64 x 32
#pragma unroll
        for (int i = 0; i < 2; i++) {
            int row = lm + 32 * i;
            size_t g = (size_t)(n0 + row) * K + k0 + lf * 4;
            float4 v = *(const float4*)&W[g];
            uint4 t;
            t.x = f2tf32(v.x); t.y = f2tf32(v.y);
            t.z = f2tf32(v.z); t.w = f2tf32(v.w);
            *(uint4*)&Bs[row * 32 + sw * 4] = t;
        }
        __syncthreads();
#pragma unroll
        for (int kk = 0; kk < 32; kk += 8) {
            uint32_t af[2][4];
#pragma unroll
            for (int mi = 0; mi < 2; mi++) {
                int r = wm + mi * 16 + lg;
                int k1 = kk + lt, k2 = k1 + 4;
                af[mi][0] = __float_as_uint(As[SWIDX(r, k1)]);
                af[mi][1] = __float_as_uint(As[SWIDX(r + 8, k1)]);
                af[mi][2] = __float_as_uint(As[SWIDX(r, k2)]);
                af[mi][3] = __float_as_uint(As[SWIDX(r + 8, k2)]);
            }
            uint32_t bf[4][2];
#pragma unroll
            for (int ni = 0; ni < 4; ni++) {
                int c = wn + ni * 8 + lg;
                int k1 = kk + lt, k2 = k1 + 4;
                bf[ni][0] = __float_as_uint(Bs[SWIDX(c, k1)]);
                bf[ni][1] = __float_as_uint(Bs[SWIDX(c, k2)]);
            }
#pragma unroll
            for (int mi = 0; mi < 2; mi++)
#pragma unroll
                for (int ni = 0; ni < 4; ni++) {
                    asm volatile(
                        "mma.sync.aligned.m16n8k8.row.col.f32.tf32.tf32.f32 "
                        "{%0,%1,%2,%3}, {%4,%5,%6,%7}, {%8,%9}, {%0,%1,%2,%3};"
                        : "+f"(acc[mi][ni][0]), "+f"(acc[mi][ni][1]),
                          "+f"(acc[mi][ni][2]), "+f"(acc[mi][ni][3])
                        : "r"(af[mi][0]), "r"(af[mi][1]),
                          "r"(af[mi][2]), "r"(af[mi][3]),
                          "r"(bf[ni][0]), "r"(bf[ni][1]));
                }
        }
        __syncthreads();
    }

    // epilogue
#pragma unroll
    for (int mi = 0; mi < 2; mi++) {
#pragma unroll
        for (int ni = 0; ni < 4; ni++) {
            int r = m0 + wm + mi * 16 + lg;
            int c = n0 + wn + ni * 8 + lt * 2;
            float b0 = bias[c], b1 = bias[c + 1];
#pragma unroll
            for (int half = 0; half < 2; half++) {
                int rr = r + half * 8;
                float v0 = (acc[mi][ni][half * 2 + 0] + b0) * alpha;
                float v1 = (acc[mi][ni][half * 2 + 1] + b1) * alpha;
                if (gelu_flag) {
                    v0 = 0.5f * v0 * (1.0f + erff(v0 * 0.70710678118654752f));
                    v1 = 0.5f * v1 * (1.0f + erff(v1 * 0.70710678118654752f));
                }
                if (res) {
                    v0 += res[(size_t)rr * N + c];
                    v1 += res[(size_t)rr * N + c + 1];
                }
                *(float2*)&C[(size_t)rr * N + c] = make_float2(v0, v1);
            }
        }
    }
}

// ---------------- flash attention ---------------------------------------
__global__ void attn_kernel(const float* __restrict__ Q,
                            const float* __restrict__ Kt,
                            const float* __restrict__ V,
                            const float* __restrict__ mask,
                            float* __restrict__ O,
                            int Lq, int Lk, float scale) {
    __shared__ float Ks[64][33];
    __shared__ float Vs[64][33];
    __shared__ float ps[8][64];
    __shared__ float qs[8][32];
    int tid = threadIdx.x;
    int w = tid >> 5, lane = tid & 31;
    int h = blockIdx.y, b = blockIdx.z;
    int qg = blockIdx.x * 8 + w;
    qs[w][lane] = Q[((size_t)(b * Lq + qg)) * E + h * KD + lane];
    const float* mrow = mask ? (mask + ((size_t)h * Lk + qg) * Lk) : nullptr;
    float m = -INFINITY, lsum = 0.f, acc = 0.f;
    int r = tid >> 3;
    int c4 = (tid & 7) * 4;
    for (int j0 = 0; j0 < Lk; j0 += 64) {
        __syncthreads();
#pragma unroll
        for (int p = 0; p < 2; p++) {
            int row = p * 32 + r;
            size_t gidx = ((size_t)(b * Lk + j0 + row)) * E + h * KD + c4;
            float4 kv = *(const float4*)&Kt[gidx];
            Ks[row][c4 + 0] = kv.x; Ks[row][c4 + 1] = kv.y;
            Ks[row][c4 + 2] = kv.z; Ks[row][c4 + 3] = kv.w;
            float4 vv = *(const float4*)&V[gidx];
            Vs[row][c4 + 0] = vv.x; Vs[row][c4 + 1] = vv.y;
            Vs[row][c4 + 2] = vv.z; Vs[row][c4 + 3] = vv.w;
        }
        __syncthreads();
        float s0 = 0.f, s1 = 0.f;
#pragma unroll
        for (int d = 0; d < 32; d++) {
            float qd = qs[w][d];
            s0 += qd * Ks[lane][d];
            s1 += qd * Ks[lane + 32][d];
        }
        s0 *= scale; s1 *= scale;
        if (mrow) { s0 += mrow[j0 + lane]; s1 += mrow[j0 + lane + 32]; }
        float cm = fmaxf(s0, s1);
#pragma unroll
        for (int o = 16; o > 0; o >>= 1)
            cm = fmaxf(cm, __shfl_xor_sync(0xffffffff, cm, o));
        float mn = fmaxf(m, cm);
        float al = expf(m - mn);
        float p0 = expf(s0 - mn), p1 = expf(s1 - mn);
        ps[w][lane] = p0; ps[w][lane + 32] = p1;
        float csum = p0 + p1;
#pragma unroll
        for (int o = 16; o > 0; o >>= 1)
            csum += __shfl_xor_sync(0xffffffff, csum, o);
        lsum = lsum * al + csum;
        acc *= al;
        __syncwarp();
#pragma unroll
        for (int j = 0; j < 64; j++)
            acc += ps[w][j] * Vs[j][lane];
        m = mn;
    }
    O[((size_t)(b * Lq + qg)) * E + h * KD + lane] = acc / lsum;
}

// ---------------- launcher ----------------------------------------------
extern "C" void kernel_launch(void* const* d_in, const int* in_sizes, int n_in,
                              void* d_out, int out_size) {
    const float* x       = (const float*)d_in[0];
    const float* queries = (const float*)d_in[1];
    const float* sn      = (const float*)d_in[2];
    const float* cs      = (const float*)d_in[3];
    const float* mask    = (const float*)d_in[4];
    const float* ln1_g   = (const float*)d_in[5];
    const float* ln1_b   = (const float*)d_in[6];
    const float* ln2_g   = (const float*)d_in[7];
    const float* ln2_b   = (const float*)d_in[8];
    const float* wq      = (const float*)d_in[9];
    const float* bq      = (const float*)d_in[10];
    const float* wk      = (const float*)d_in[11];
    const float* bk      = (const float*)d_in[12];
    const float* wv      = (const float*)d_in[13];
    const float* bv      = (const float*)d_in[14];
    const float* lepe_w  = (const float*)d_in[15];
    const float* lepe_b  = (const float*)d_in[16];
    const float* wo      = (const float*)d_in[17];
    const float* bo      = (const float*)d_in[18];
    const float* fc1_w   = (const float*)d_in[19];
    const float* fc1_b   = (const float*)d_in[20];
    const float* fc2_w   = (const float*)d_in[21];
    const float* fc2_b   = (const float*)d_in[22];
    const float* pos_w   = (const float*)d_in[23];
    const float* pos_b   = (const float*)d_in[24];
    const float* ca_in_w = (const float*)d_in[25];
    const float* ca_in_b = (const float*)d_in[26];
    const float* ca_out_w= (const float*)d_in[27];
    const float* ca_out_b= (const float*)d_in[28];

    void* sp = nullptr;
    cudaGetSymbolAddress(&sp, g_scratch);
    float* S = (float*)sp;
    float* X1   = S + OFF_X1;
    float* HN   = S + OFF_HN;
    float* Qb   = S + OFF_Q;
    float* Kb   = S + OFF_K;
    float* Vb   = S + OFF_V;
    float* LEPE = S + OFF_LEPE;
    float* AO   = S + OFF_AO;
    float* X2   = S + OFF_X2;
    float* FF   = S + OFF_FF;
    float* CK   = S + OFF_CK;
    float* CV   = S + OFF_CV;
    float* CQ   = S + OFF_CQ;
    float* CAO  = S + OFF_CAO;
    float* Q2   = S + OFF_Q2;
    float* QLN  = S + OFF_QLN;
    float* QLN2 = S + OFF_QLN2;
    float* QFF  = S + OFF_QFF;

    float* OX = (float*)d_out;            // x output: B*L*E
    float* OQ = OX + (size_t)Bb * L * E;  // queries output: B*NQ*E

    const int MTOK = Bb * L;   // 8192
    const int MQ   = Bb * NQ;  // 512
    dim3 sp3(WW, HH, Bb);

    // 1. x = x + dwconv3x3(x)
    dwconv_kernel<3, true><<<sp3, 256>>>(x, pos_w, pos_b, X1);
    // 2. hn = LN1(x)
    ln_kernel<<<MTOK, 256>>>(X1, ln1_g, ln1_b, HN);
    // 3. q, k (pre-scaled), v
    mma_gemm_kernel<<<dim3(E/64, MTOK/128), 256>>>(HN, nullptr, wq, bq, nullptr, Qb, MTOK, E, E, 1.f, 0);
    mma_gemm_kernel<<<dim3(E/64, MTOK/128), 256>>>(HN, nullptr, wk, bk, nullptr, Kb, MTOK, E, E, SCALING, 0);
    mma_gemm_kernel<<<dim3(E/64, MTOK/128), 256>>>(HN, nullptr, wv, bv, nullptr, Vb, MTOK, E, E, 1.f, 0);
    // 4. lepe = dwconv5x5(v)
    dwconv_kernel<5, false><<<sp3, 256>>>(Vb, lepe_w, lepe_b, LEPE);
    // 5. theta shift q, k
    theta_kernel<<<(Bb * L * (E/2) + 255) / 256, 256>>>(Qb, Kb, sn, cs);
    // 6. self attention (k pre-scaled, additive mask)
    attn_kernel<<<dim3(L/8, HEADS, Bb), 256>>>(Qb, Kb, Vb, mask, AO, L, L, 1.f);
    // 7. x = x + (attn_out + lepe) @ wo^T + bo
    mma_gemm_kernel<<<dim3(E/64, MTOK/128), 256>>>(AO, LEPE, wo, bo, X1, X2, MTOK, E, E, 1.f, 0);
    // 8. FFN on x
    ln_kernel<<<MTOK, 256>>>(X2, ln2_g, ln2_b, HN);
    mma_gemm_kernel<<<dim3(FFN/64, MTOK/128), 256>>>(HN, nullptr, fc1_w, fc1_b, nullptr, FF, MTOK, FFN, E, 1.f, 1);
    mma_gemm_kernel<<<dim3(E/64, MTOK/128), 256>>>(FF, nullptr, fc2_w, fc2_b, X2, OX, MTOK, E, FFN, 1.f, 0);
    // 9. cross attention: q from LN1(queries); k,v from xs = final x
    ln_kernel<<<MQ, 256>>>(queries, ln1_g, ln1_b, QLN);
    mma_gemm_kernel<<<dim3(E/64, MQ/128), 256>>>(QLN, nullptr, ca_in_w,           ca_in_b,       nullptr, CQ, MQ,   E, E, 1.f, 0);
    mma_gemm_kernel<<<dim3(E/64, MTOK/128), 256>>>(OX, nullptr, ca_in_w + E*E,    ca_in_b + E,   nullptr, CK, MTOK, E, E, 1.f, 0);
    mma_gemm_kernel<<<dim3(E/64, MTOK/128), 256>>>(OX, nullptr, ca_in_w + 2*E*E,  ca_in_b + 2*E, nullptr, CV, MTOK, E, E, 1.f, 0);
    attn_kernel<<<dim3(NQ/8, HEADS, Bb), 256>>>(CQ, CK, CV, nullptr, CAO, NQ, L, SCALING);
    mma_gemm_kernel<<<dim3(E/64, MQ/128), 256>>>(CAO, nullptr, ca_out_w, ca_out_b, queries, Q2, MQ, E, E, 1.f, 0);
    // 10. FFN on queries
    ln_kernel<<<MQ, 256>>>(Q2, ln2_g, ln2_b, QLN2);
    mma_gemm_kernel<<<dim3(FFN/64, MQ/128), 256>>>(QLN2, nullptr, fc1_w, fc1_b, nullptr, QFF, MQ, FFN, E, 1.f, 1);
    mma_gemm_kernel<<<dim3(E/64, MQ/128), 256>>>(QFF, nullptr, fc2_w, fc2_b, Q2, OQ, MQ, E, FFN, 1.f, 0);
}

// round 3
// speedup vs baseline: 2.5551x; 1.9090x over previous
#include <cuda_runtime.h>
#include <math.h>
#include <stdint.h>

#define Bb 8
#define HH 32
#define WW 32
#define E 256
#define HEADS 8
#define KD 32
#define FFN 1024
#define NQ 64
#define L 1024
#define SCALING 0.17677669529663687f
#define LOG2E 1.4426950408889634f

// ---------------- scratch arena (no allocations allowed) ----------------
#define SZ_TOK (Bb * L * E)
#define SZ_QTK (Bb * NQ * E)
#define OFF_X1   ((size_t)0)
#define OFF_HN   (OFF_X1   + SZ_TOK)
#define OFF_Q    (OFF_HN   + SZ_TOK)
#define OFF_K    (OFF_Q    + SZ_TOK)
#define OFF_V    (OFF_K    + SZ_TOK)
#define OFF_LEPE (OFF_V    + SZ_TOK)
#define OFF_AO   (OFF_LEPE + SZ_TOK)
#define OFF_X2   (OFF_AO   + SZ_TOK)
#define OFF_FF   (OFF_X2   + SZ_TOK)
#define OFF_CK   (OFF_FF   + (size_t)Bb * L * FFN)
#define OFF_CV   (OFF_CK   + SZ_TOK)
#define OFF_CQ   (OFF_CV   + SZ_TOK)
#define OFF_CAO  (OFF_CQ   + SZ_QTK)
#define OFF_Q2   (OFF_CAO  + SZ_QTK)
#define OFF_QLN  (OFF_Q2   + SZ_QTK)
#define OFF_QLN2 (OFF_QLN  + SZ_QTK)
#define OFF_QFF  (OFF_QLN2 + SZ_QTK)
#define SCRATCH_TOTAL (OFF_QFF + (size_t)Bb * NQ * FFN)

__device__ float g_scratch[SCRATCH_TOTAL];

// ---------------- depthwise conv -----------------------------------------
template <int KS, bool ADDIN>
__global__ void dwconv_kernel(const float* __restrict__ in,
                              const float* __restrict__ w,
                              const float* __restrict__ bias,
                              float* __restrict__ out) {
    const int P = KS / 2;
    int c = threadIdx.x;
    int wx = blockIdx.x, hy = blockIdx.y, b = blockIdx.z;
    float acc = bias[c];
#pragma unroll
    for (int kh = 0; kh < KS; kh++) {
        int y = hy + kh - P;
        if (y < 0 || y >= HH) continue;
#pragma unroll
        for (int kw = 0; kw < KS; kw++) {
            int xx = wx + kw - P;
            if (xx < 0 || xx >= WW) continue;
            acc += in[(((size_t)b * HH + y) * WW + xx) * E + c] *
                   w[c * KS * KS + kh * KS + kw];
        }
    }
    size_t o = (((size_t)b * HH + hy) * WW + wx) * E + c;
    out[o] = ADDIN ? (in[o] + acc) : acc;
}

// ---------------- layernorm ----------------------------------------------
__global__ void ln_kernel(const float* __restrict__ in,
                          const float* __restrict__ g,
                          const float* __restrict__ b,
                          float* __restrict__ out) {
    int row = blockIdx.x;
    int t = threadIdx.x;
    float v = in[(size_t)row * E + t];
    __shared__ float s1[256], s2[256];
    s1[t] = v; s2[t] = v * v;
    __syncthreads();
    for (int o = 128; o > 0; o >>= 1) {
        if (t < o) { s1[t] += s1[t + o]; s2[t] += s2[t + o]; }
        __syncthreads();
    }
    float m = s1[0] * (1.0f / E);
    float var = s2[0] * (1.0f / E) - m * m;
    float inv = rsqrtf(var + 1e-6f);
    out[(size_t)row * E + t] = (v - m) * inv * g[t] + b[t];
}

// ---------------- theta shift --------------------------------------------
__global__ void theta_kernel(float* __restrict__ q, float* __restrict__ k,
                             const float* __restrict__ sn,
                             const float* __restrict__ cs) {
    int idx = blockIdx.x * blockDim.x + threadIdx.x;
    if (idx >= Bb * L * (E / 2)) return;
    int e0 = (idx % (E / 2)) * 2;
    int bl = idx / (E / 2);
    int l = bl % L;
    int dd0 = e0 & 31;
    int sidx = l * KD + dd0;
    float s0 = sn[sidx], c0 = cs[sidx], s1 = sn[sidx + 1], c1 = cs[sidx + 1];
    size_t base = (size_t)bl * E + e0;
    float q0 = q[base], q1 = q[base + 1];
    q[base]     = q0 * c0 - q1 * s0;
    q[base + 1] = q1 * c1 + q0 * s1;
    float k0 = k[base], k1 = k[base + 1];
    k[base]     = k0 * c0 - k1 * s0;
    k[base + 1] = k1 * c1 + k0 * s1;
}

// ---------------- tf32 helpers -------------------------------------------
__device__ __forceinline__ uint32_t f2tf32(float x) {
    uint32_t r;
    asm("cvt.rna.tf32.f32 %0, %1;" : "=r"(r) : "f"(x));
    return r;
}
#define SWIDX(r, k) (((r) << 5) + (((((k) >> 2) ^ ((r) & 7))) << 2) + ((k) & 3))

#define MMA_TF32(acc, a0, a1, a2, a3, b0, b1)                               \
    asm volatile(                                                           \
        "mma.sync.aligned.m16n8k8.row.col.f32.tf32.tf32.f32 "               \
        "{%0,%1,%2,%3}, {%4,%5,%6,%7}, {%8,%9}, {%0,%1,%2,%3};"             \
        : "+f"(acc[0]), "+f"(acc[1]), "+f"(acc[2]), "+f"(acc[3])            \
        : "r"(a0), "r"(a1), "r"(a2), "r"(a3), "r"(b0), "r"(b1))

// ---------------- tf32 tensor-core GEMM (from R2) ------------------------
__global__ void mma_gemm_kernel(const float* __restrict__ A,
                                const float* __restrict__ A2,
                                const float* __restrict__ W,
                                const float* __restrict__ bias,
                                const float* __restrict__ res,
                                float* __restrict__ C,
                                int M, int N, int K, float alpha, int gelu_flag) {
    __shared__ float As[128 * 32];
    __shared__ float Bs[64 * 32];
    int tid = threadIdx.x;
    int w = tid >> 5, lane = tid & 31;
    int wm = (w & 3) * 32, wn = (w >> 2) * 32;
    int m0 = blockIdx.y * 128, n0 = blockIdx.x * 64;
    int lm = tid >> 3;
    int lf = tid & 7;
    int lg = lane >> 2;
    int lt = lane & 3;
    int sw = lf ^ (lm & 7);

    float acc[2][4][4] = {};

    for (int k0 = 0; k0 < K; k0 += 32) {
#pragma unroll
        for (int i = 0; i < 4; i++) {
            int row = lm + 32 * i;
            size_t g = (size_t)(m0 + row) * K + k0 + lf * 4;
            float4 v = *(const float4*)&A[g];
            if (A2) {
                float4 u = *(const float4*)&A2[g];
                v.x += u.x; v.y += u.y; v.z += u.z; v.w += u.w;
            }
            uint4 t;
            t.x = f2tf32(v.x); t.y = f2tf32(v.y);
            t.z = f2tf32(v.z); t.w = f2tf32(v.w);
            *(uint4*)&As[row * 32 + sw * 4] = t;
        }
#pragma unroll
        for (int i = 0; i < 2; i++) {
            int row = lm + 32 * i;
            size_t g = (size_t)(n0 + row) * K + k0 + lf * 4;
            float4 v = *(const float4*)&W[g];
            uint4 t;
            t.x = f2tf32(v.x); t.y = f2tf32(v.y);
            t.z = f2tf32(v.z); t.w = f2tf32(v.w);
            *(uint4*)&Bs[row * 32 + sw * 4] = t;
        }
        __syncthreads();
#pragma unroll
        for (int kk = 0; kk < 32; kk += 8) {
            uint32_t af[2][4];
#pragma unroll
            for (int mi = 0; mi < 2; mi++) {
                int r = wm + mi * 16 + lg;
                int k1 = kk + lt, k2 = k1 + 4;
                af[mi][0] = __float_as_uint(As[SWIDX(r, k1)]);
                af[mi][1] = __float_as_uint(As[SWIDX(r + 8, k1)]);
                af[mi][2] = __float_as_uint(As[SWIDX(r, k2)]);
                af[mi][3] = __float_as_uint(As[SWIDX(r + 8, k2)]);
            }
            uint32_t bf[4][2];
#pragma unroll
            for (int ni = 0; ni < 4; ni++) {
                int c = wn + ni * 8 + lg;
                int k1 = kk + lt, k2 = k1 + 4;
                bf[ni][0] = __float_as_uint(Bs[SWIDX(c, k1)]);
                bf[ni][1] = __float_as_uint(Bs[SWIDX(c, k2)]);
            }
#pragma unroll
            for (int mi = 0; mi < 2; mi++)
#pragma unroll
                for (int ni = 0; ni < 4; ni++)
                    MMA_TF32(acc[mi][ni], af[mi][0], af[mi][1], af[mi][2],
                             af[mi][3], bf[ni][0], bf[ni][1]);
        }
        __syncthreads();
    }

#pragma unroll
    for (int mi = 0; mi < 2; mi++) {
#pragma unroll
        for (int ni = 0; ni < 4; ni++) {
            int r = m0 + wm + mi * 16 + lg;
            int c = n0 + wn + ni * 8 + lt * 2;
            float b0 = bias[c], b1 = bias[c + 1];
#pragma unroll
            for (int half = 0; half < 2; half++) {
                int rr = r + half * 8;
                float v0 = (acc[mi][ni][half * 2 + 0] + b0) * alpha;
                float v1 = (acc[mi][ni][half * 2 + 1] + b1) * alpha;
                if (gelu_flag) {
                    v0 = 0.5f * v0 * (1.0f + erff(v0 * 0.70710678118654752f));
                    v1 = 0.5f * v1 * (1.0f + erff(v1 * 0.70710678118654752f));
                }
                if (res) {
                    v0 += res[(size_t)rr * N + c];
                    v1 += res[(size_t)rr * N + c + 1];
                }
                *(float2*)&C[(size_t)rr * N + c] = make_float2(v0, v1);
            }
        }
    }
}

// ---------------- tensor-core flash attention ----------------------------
// One block per (64-query tile, head, batch). 4 warps x 16 rows.
// S = Q@K^T (tf32 mma), fused *scale + mask, online softmax in regs,
// P via smem slab (per-warp rows), O += P@V (tf32 mma).
#define PSTRIDE 66
__global__ __launch_bounds__(128) void attn_tc_kernel(
        const float* __restrict__ Q, const float* __restrict__ Kt,
        const float* __restrict__ V, const float* __restrict__ mask,
        float* __restrict__ O, int Lq, int Lk, float scale) {
    __shared__ float Qs[64 * 32];
    __shared__ float Ks[64 * 32];
    __shared__ float Vs[64 * 32];
    __shared__ float Ps[64 * PSTRIDE];

    int tid = threadIdx.x;
    int w = tid >> 5, lane = tid & 31;
    int lg = lane >> 2, lt = lane & 3;
    int h = blockIdx.y, b = blockIdx.z;
    int q0 = blockIdx.x * 64;
    int wm = w * 16;

    // loader indexing: 64 rows x 8 float4-slots, 128 threads -> 4 slots each
    int lrow = tid & 63;
    int ls0 = (tid >> 6) * 4;  // 0 or 4

    // ---- load Q tile (64x32) swizzled tf32 ----
    {
        const float* src = Q + ((size_t)(b * Lq + q0 + lrow)) * E + h * KD;
#pragma unroll
        for (int s = 0; s < 4; s++) {
            int f = ls0 + s;
            float4 v = *(const float4*)&src[f * 4];
            uint4 t;
            t.x = f2tf32(v.x); t.y = f2tf32(v.y);
            t.z = f2tf32(v.z); t.w = f2tf32(v.w);
            *(uint4*)&Qs[lrow * 32 + (f ^ (lrow & 7)) * 4] = t;
        }
    }

    float m0 = -INFINITY, m1 = -INFINITY, l0 = 0.f, l1 = 0.f;
    float oacc[4][4] = {};

    const float* mbase = mask ? (mask + ((size_t)h * Lk + q0) * Lk) : nullptr;

    for (int j0 = 0; j0 < Lk; j0 += 64) {
        __syncthreads();
        // ---- load K, V chunks (64x32 each) swizzled tf32 ----
        {
            const float* ksrc = Kt + ((size_t)(b * Lk + j0 + lrow)) * E + h * KD;
            const float* vsrc = V  + ((size_t)(b * Lk + j0 + lrow)) * E + h * KD;
#pragma unroll
            for (int s = 0; s < 4; s++) {
                int f = ls0 + s;
                int dst = lrow * 32 + (f ^ (lrow & 7)) * 4;
                float4 kv = *(const float4*)&ksrc[f * 4];
                uint4 t;
                t.x = f2tf32(kv.x); t.y = f2tf32(kv.y);
                t.z = f2tf32(kv.z); t.w = f2tf32(kv.w);
                *(uint4*)&Ks[dst] = t;
                float4 vv = *(const float4*)&vsrc[f * 4];
                uint4 u;
                u.x = f2tf32(vv.x); u.y = f2tf32(vv.y);
                u.z = f2tf32(vv.z); u.w = f2tf32(vv.w);
                *(uint4*)&Vs[dst] = u;
            }
        }
        __syncthreads();

        // ---- S = Q @ K^T : 16x64 per warp ----
        float sacc[8][4];
#pragma unroll
        for (int ni = 0; ni < 8; ni++)
#pragma unroll
            for (int c = 0; c < 4; c++) sacc[ni][c] = 0.f;
#pragma unroll
        for (int kk = 0; kk < 32; kk += 8) {
            int k1 = kk + lt, k2 = k1 + 4;
            uint32_t a0 = __float_as_uint(Qs[SWIDX(wm + lg, k1)]);
            uint32_t a1 = __float_as_uint(Qs[SWIDX(wm + 8 + lg, k1)]);
            uint32_t a2 = __float_as_uint(Qs[SWIDX(wm + lg, k2)]);
            uint32_t a3 = __float_as_uint(Qs[SWIDX(wm + 8 + lg, k2)]);
#pragma unroll
            for (int ni = 0; ni < 8; ni++) {
                uint32_t b0 = __float_as_uint(Ks[SWIDX(ni * 8 + lg, k1)]);
                uint32_t b1 = __float_as_uint(Ks[SWIDX(ni * 8 + lg, k2)]);
                MMA_TF32(sacc[ni], a0, a1, a2, a3, b0, b1);
            }
        }

        // ---- scale + mask ----
        if (mbase) {
            int r0 = wm + lg, r1 = wm + 8 + lg;
#pragma unroll
            for (int ni = 0; ni < 8; ni++) {
                int c = j0 + ni * 8 + lt * 2;
                float2 mv0 = *(const float2*)&mbase[(size_t)r0 * Lk + c];
                float2 mv1 = *(const float2*)&mbase[(size_t)r1 * Lk + c];
                sacc[ni][0] = sacc[ni][0] * scale + mv0.x;
                sacc[ni][1] = sacc[ni][1] * scale + mv0.y;
                sacc[ni][2] = sacc[ni][2] * scale + mv1.x;
                sacc[ni][3] = sacc[ni][3] * scale + mv1.y;
            }
        } else if (scale != 1.f) {
#pragma unroll
            for (int ni = 0; ni < 8; ni++)
#pragma unroll
                for (int c = 0; c < 4; c++) sacc[ni][c] *= scale;
        }

        // ---- online softmax ----
        float rm0 = -INFINITY, rm1 = -INFINITY;
#pragma unroll
        for (int ni = 0; ni < 8; ni++) {
            rm0 = fmaxf(rm0, fmaxf(sacc[ni][0], sacc[ni][1]));
            rm1 = fmaxf(rm1, fmaxf(sacc[ni][2], sacc[ni][3]));
        }
        rm0 = fmaxf(rm0, __shfl_xor_sync(0xffffffff, rm0, 1));
        rm0 = fmaxf(rm0, __shfl_xor_sync(0xffffffff, rm0, 2));
        rm1 = fmaxf(rm1, __shfl_xor_sync(0xffffffff, rm1, 1));
        rm1 = fmaxf(rm1, __shfl_xor_sync(0xffffffff, rm1, 2));
        float mn0 = fmaxf(m0, rm0), mn1 = fmaxf(m1, rm1);
        float al0 = exp2f((m0 - mn0) * LOG2E);
        float al1 = exp2f((m1 - mn1) * LOG2E);
        float rs0 = 0.f, rs1 = 0.f;
#pragma unroll
        for (int ni = 0; ni < 8; ni++) {
            float p0 = exp2f((sacc[ni][0] - mn0) * LOG2E);
            float p1 = exp2f((sacc[ni][1] - mn0) * LOG2E);
            float p2 = exp2f((sacc[ni][2] - mn1) * LOG2E);
            float p3 = exp2f((sacc[ni][3] - mn1) * LOG2E);
            rs0 += p0 + p1; rs1 += p2 + p3;
            int c = ni * 8 + lt * 2;
            *(float2*)&Ps[(wm + lg) * PSTRIDE + c]     = make_float2(p0, p1);
            *(float2*)&Ps[(wm + 8 + lg) * PSTRIDE + c] = make_float2(p2, p3);
        }
        rs0 += __shfl_xor_sync(0xffffffff, rs0, 1);
        rs0 += __shfl_xor_sync(0xffffffff, rs0, 2);
        rs1 += __shfl_xor_sync(0xffffffff, rs1, 1);
        rs1 += __shfl_xor_sync(0xffffffff, rs1, 2);
        l0 = l0 * al0 + rs0;
        l1 = l1 * al1 + rs1;
        m0 = mn0; m1 = mn1;
#pragma unroll
        for (int ni = 0; ni < 4; ni++) {
            oacc[ni][0] *= al0; oacc[ni][1] *= al0;
            oacc[ni][2] *= al1; oacc[ni][3] *= al1;
        }
        __syncwarp();

        // ---- O += P @ V : K-dim = 64 keys ----
#pragma unroll
        for (int kk = 0; kk < 64; kk += 8) {
            int k1 = kk + lt, k2 = k1 + 4;
            uint32_t a0 = f2tf32(Ps[(wm + lg) * PSTRIDE + k1]);
            uint32_t a1 = f2tf32(Ps[(wm + 8 + lg) * PSTRIDE + k1]);
            uint32_t a2 = f2tf32(Ps[(wm + lg) * PSTRIDE + k2]);
            uint32_t a3 = f2tf32(Ps[(wm + 8 + lg) * PSTRIDE + k2]);
#pragma unroll
            for (int ni = 0; ni < 4; ni++) {
                uint32_t b0 = __float_as_uint(Vs[SWIDX(k1, ni * 8 + lg)]);
                uint32_t b1 = __float_as_uint(Vs[SWIDX(k2, ni * 8 + lg)]);
                MMA_TF32(oacc[ni], a0, a1, a2, a3, b0, b1);
            }
        }
    }

    // ---- finalize ----
    float inv0 = 1.f / l0, inv1 = 1.f / l1;
    int r0 = q0 + wm + lg, r1 = r0 + 8;
#pragma unroll
    for (int ni = 0; ni < 4; ni++) {
        int c = h * KD + ni * 8 + lt * 2;
        *(float2*)&O[((size_t)(b * Lq + r0)) * E + c] =
            make_float2(oacc[ni][0] * inv0, oacc[ni][1] * inv0);
        *(float2*)&O[((size_t)(b * Lq + r1)) * E + c] =
            make_float2(oacc[ni][2] * inv1, oacc[ni][3] * inv1);
    }
}

// ---------------- launcher ----------------------------------------------
extern "C" void kernel_launch(void* const* d_in, const int* in_sizes, int n_in,
                              void* d_out, int out_size) {
    const float* x       = (const float*)d_in[0];
    const float* queries = (const float*)d_in[1];
    const float* sn      = (const float*)d_in[2];
    const float* cs      = (const float*)d_in[3];
    const float* mask    = (const float*)d_in[4];
    const float* ln1_g   = (const float*)d_in[5];
    const float* ln1_b   = (const float*)d_in[6];
    const float* ln2_g   = (const float*)d_in[7];
    const float* ln2_b   = (const float*)d_in[8];
    const float* wq      = (const float*)d_in[9];
    const float* bq      = (const float*)d_in[10];
    const float* wk      = (const float*)d_in[11];
    const float* bk      = (const float*)d_in[12];
    const float* wv      = (const float*)d_in[13];
    const float* bv      = (const float*)d_in[14];
    const float* lepe_w  = (const float*)d_in[15];
    const float* lepe_b  = (const float*)d_in[16];
    const float* wo      = (const float*)d_in[17];
    const float* bo      = (const float*)d_in[18];
    const float* fc1_w   = (const float*)d_in[19];
    const float* fc1_b   = (const float*)d_in[20];
    const float* fc2_w   = (const float*)d_in[21];
    const float* fc2_b   = (const float*)d_in[22];
    const float* pos_w   = (const float*)d_in[23];
    const float* pos_b   = (const float*)d_in[24];
    const float* ca_in_w = (const float*)d_in[25];
    const float* ca_in_b = (const float*)d_in[26];
    const float* ca_out_w= (const float*)d_in[27];
    const float* ca_out_b= (const float*)d_in[28];

    void* sp = nullptr;
    cudaGetSymbolAddress(&sp, g_scratch);
    float* S = (float*)sp;
    float* X1   = S + OFF_X1;
    float* HN   = S + OFF_HN;
    float* Qb   = S + OFF_Q;
    float* Kb   = S + OFF_K;
    float* Vb   = S + OFF_V;
    float* LEPE = S + OFF_LEPE;
    float* AO   = S + OFF_AO;
    float* X2   = S + OFF_X2;
    float* FF   = S + OFF_FF;
    float* CK   = S + OFF_CK;
    float* CV   = S + OFF_CV;
    float* CQ   = S + OFF_CQ;
    float* CAO  = S + OFF_CAO;
    float* Q2   = S + OFF_Q2;
    float* QLN  = S + OFF_QLN;
    float* QLN2 = S + OFF_QLN2;
    float* QFF  = S + OFF_QFF;

    float* OX = (float*)d_out;
    float* OQ = OX + (size_t)Bb * L * E;

    const int MTOK = Bb * L;   // 8192
    const int MQ   = Bb * NQ;  // 512
    dim3 sp3(WW, HH, Bb);

    dwconv_kernel<3, true><<<sp3, 256>>>(x, pos_w, pos_b, X1);
    ln_kernel<<<MTOK, 256>>>(X1, ln1_g, ln1_b, HN);
    mma_gemm_kernel<<<dim3(E/64, MTOK/128), 256>>>(HN, nullptr, wq, bq, nullptr, Qb, MTOK, E, E, 1.f, 0);
    mma_gemm_kernel<<<dim3(E/64, MTOK/128), 256>>>(HN, nullptr, wk, bk, nullptr, Kb, MTOK, E, E, SCALING, 0);
    mma_gemm_kernel<<<dim3(E/64, MTOK/128), 256>>>(HN, nullptr, wv, bv, nullptr, Vb, MTOK, E, E, 1.f, 0);
    dwconv_kernel<5, false><<<sp3, 256>>>(Vb, lepe_w, lepe_b, LEPE);
    theta_kernel<<<(Bb * L * (E/2) + 255) / 256, 256>>>(Qb, Kb, sn, cs);
    attn_tc_kernel<<<dim3(L/64, HEADS, Bb), 128>>>(Qb, Kb, Vb, mask, AO, L, L, 1.f);
    mma_gemm_kernel<<<dim3(E/64, MTOK/128), 256>>>(AO, LEPE, wo, bo, X1, X2, MTOK, E, E, 1.f, 0);
    ln_kernel<<<MTOK, 256>>>(X2, ln2_g, ln2_b, HN);
    mma_gemm_kernel<<<dim3(FFN/64, MTOK/128), 256>>>(HN, nullptr, fc1_w, fc1_b, nullptr, FF, MTOK, FFN, E, 1.f, 1);
    mma_gemm_kernel<<<dim3(E/64, MTOK/128), 256>>>(FF, nullptr, fc2_w, fc2_b, X2, OX, MTOK, E, FFN, 1.f, 0);
    ln_kernel<<<MQ, 256>>>(queries, ln1_g, ln1_b, QLN);
    mma_gemm_kernel<<<dim3(E/64, MQ/128), 256>>>(QLN, nullptr, ca_in_w,           ca_in_b,       nullptr, CQ, MQ,   E, E, 1.f, 0);
    mma_gemm_kernel<<<dim3(E/64, MTOK/128), 256>>>(OX, nullptr, ca_in_w + E*E,    ca_in_b + E,   nullptr, CK, MTOK, E, E, 1.f, 0);
    mma_gemm_kernel<<<dim3(E/64, MTOK/128), 256>>>(OX, nullptr, ca_in_w + 2*E*E,  ca_in_b + 2*E, nullptr, CV, MTOK, E, E, 1.f, 0);
    attn_tc_kernel<<<dim3(NQ/64, HEADS, Bb), 128>>>(CQ, CK, CV, nullptr, CAO, NQ, L, SCALING);
    mma_gemm_kernel<<<dim3(E/64, MQ/128), 256>>>(CAO, nullptr, ca_out_w, ca_out_b, queries, Q2, MQ, E, E, 1.f, 0);
    ln_kernel<<<MQ, 256>>>(Q2, ln2_g, ln2_b, QLN2);
    mma_gemm_kernel<<<dim3(FFN/64, MQ/128), 256>>>(QLN2, nullptr, fc1_w, fc1_b, nullptr, QFF, MQ, FFN, E, 1.f, 1);
    mma_gemm_kernel<<<dim3(E/64, MQ/128), 256>>>(QFF, nullptr, fc2_w, fc2_b, Q2, OQ, MQ, E, FFN, 1.f, 0);
}

// round 4
// speedup vs baseline: 3.6296x; 1.4205x over previous
#include <cuda_runtime.h>
#include <math.h>
#include <stdint.h>

#define Bb 8
#define HH 32
#define WW 32
#define E 256
#define HEADS 8
#define KD 32
#define FFN 1024
#define NQ 64
#define L 1024
#define SCALING 0.17677669529663687f
#define LOG2E 1.4426950408889634f

#define EPI_NONE 0
#define EPI_GELU 1
#define EPI_THETA 2

// ---------------- scratch arena ----------------
#define SZ_TOK (Bb * L * E)
#define SZ_QTK (Bb * NQ * E)
#define OFF_X1   ((size_t)0)
#define OFF_HN   (OFF_X1   + SZ_TOK)
#define OFF_Q    (OFF_HN   + SZ_TOK)
#define OFF_K    (OFF_Q    + SZ_TOK)
#define OFF_V    (OFF_K    + SZ_TOK)
#define OFF_LEPE (OFF_V    + SZ_TOK)
#define OFF_AO   (OFF_LEPE + SZ_TOK)
#define OFF_X2   (OFF_AO   + SZ_TOK)
#define OFF_FF   (OFF_X2   + SZ_TOK)
#define OFF_CK   (OFF_FF   + (size_t)Bb * L * FFN)
#define OFF_CV   (OFF_CK   + SZ_TOK)
#define OFF_CQ   (OFF_CV   + SZ_TOK)
#define OFF_CAO  (OFF_CQ   + SZ_QTK)
#define OFF_Q2   (OFF_CAO  + SZ_QTK)
#define OFF_QLN  (OFF_Q2   + SZ_QTK)
#define OFF_QLN2 (OFF_QLN  + SZ_QTK)
#define OFF_QFF  (OFF_QLN2 + SZ_QTK)
#define SCRATCH_TOTAL (OFF_QFF + (size_t)Bb * NQ * FFN)

__device__ float g_scratch[SCRATCH_TOTAL];

// ---------------- async copy helpers ----------------
__device__ __forceinline__ void cp16(float* dst, const float* src) {
    uint32_t d = (uint32_t)__cvta_generic_to_shared(dst);
    asm volatile("cp.async.cg.shared.global [%0], [%1], 16;" :: "r"(d), "l"(src));
}
#define CP_COMMIT() asm volatile("cp.async.commit_group;" ::: "memory")
#define CP_WAIT(N)  asm volatile("cp.async.wait_group %0;" :: "n"(N) : "memory")

#define SWIDX(r, k) (((r) << 5) + (((((k) >> 2) ^ ((r) & 7))) << 2) + ((k) & 3))

#define MMA_TF32(acc, a0, a1, a2, a3, b0, b1)                               \
    asm volatile(                                                           \
        "mma.sync.aligned.m16n8k8.row.col.f32.tf32.tf32.f32 "               \
        "{%0,%1,%2,%3}, {%4,%5,%6,%7}, {%8,%9}, {%0,%1,%2,%3};"             \
        : "+f"(acc[0]), "+f"(acc[1]), "+f"(acc[2]), "+f"(acc[3])            \
        : "r"(a0), "r"(a1), "r"(a2), "r"(a3), "r"(b0), "r"(b1))

// ---------------- GEMM core: C = epi(A @ W^T) ------------------------
// Block tile 128x64, k-tile 32, double-buffered cp.async, 8 warps 32x32.
__device__ __forceinline__ void gemm_core(
        const float* __restrict__ A, const float* __restrict__ W,
        const float* __restrict__ bias, const float* __restrict__ res,
        float* __restrict__ C, int M, int N, int K, float alpha, int epi,
        const float* __restrict__ sn, const float* __restrict__ cs,
        float* As, float* Bs) {
    int tid = threadIdx.x;
    int w = tid >> 5, lane = tid & 31;
    int wm = (w & 3) * 32, wn = (w >> 2) * 32;
    int m0 = blockIdx.y * 128, n0 = blockIdx.x * 64;
    int lg = lane >> 2, lt = lane & 3;

    float acc[2][4][4] = {};

    auto loadTile = [&](int buf, int k0) {
        float* Ab = As + buf * 4096;
        float* Bd = Bs + buf * 2048;
#pragma unroll
        for (int i = 0; i < 4; i++) {
            int id = tid + 256 * i;
            int row = id >> 3, f = id & 7;
            cp16(&Ab[row * 32 + ((f ^ (row & 7)) << 2)],
                 &A[(size_t)(m0 + row) * K + k0 + f * 4]);
        }
#pragma unroll
        for (int i = 0; i < 2; i++) {
            int id = tid + 256 * i;
            int row = id >> 3, f = id & 7;
            cp16(&Bd[row * 32 + ((f ^ (row & 7)) << 2)],
                 &W[(size_t)(n0 + row) * K + k0 + f * 4]);
        }
    };

    int KT = K >> 5;
    int buf = 0;
    loadTile(0, 0);
    CP_COMMIT();
    for (int kt = 0; kt < KT; kt++) {
        if (kt + 1 < KT) {
            loadTile(buf ^ 1, (kt + 1) << 5);
            CP_COMMIT();
            CP_WAIT(1);
        } else {
            CP_WAIT(0);
        }
        __syncthreads();
        const float* Ab = As + buf * 4096;
        const float* Bd = Bs + buf * 2048;
#pragma unroll
        for (int kk = 0; kk < 32; kk += 8) {
            int k1 = kk + lt, k2 = k1 + 4;
            uint32_t af[2][4];
#pragma unroll
            for (int mi = 0; mi < 2; mi++) {
                int r = wm + mi * 16 + lg;
                af[mi][0] = __float_as_uint(Ab[SWIDX(r, k1)]);
                af[mi][1] = __float_as_uint(Ab[SWIDX(r + 8, k1)]);
                af[mi][2] = __float_as_uint(Ab[SWIDX(r, k2)]);
                af[mi][3] = __float_as_uint(Ab[SWIDX(r + 8, k2)]);
            }
            uint32_t bf[4][2];
#pragma unroll
            for (int ni = 0; ni < 4; ni++) {
                int c = wn + ni * 8 + lg;
                bf[ni][0] = __float_as_uint(Bd[SWIDX(c, k1)]);
                bf[ni][1] = __float_as_uint(Bd[SWIDX(c, k2)]);
            }
#pragma unroll
            for (int mi = 0; mi < 2; mi++)
#pragma unroll
                for (int ni = 0; ni < 4; ni++)
                    MMA_TF32(acc[mi][ni], af[mi][0], af[mi][1], af[mi][2],
                             af[mi][3], bf[ni][0], bf[ni][1]);
        }
        __syncthreads();
        buf ^= 1;
    }

    // epilogue
#pragma unroll
    for (int mi = 0; mi < 2; mi++) {
#pragma unroll
        for (int ni = 0; ni < 4; ni++) {
            int r = m0 + wm + mi * 16 + lg;
            int c = n0 + wn + ni * 8 + lt * 2;
            float b0 = bias[c], b1 = bias[c + 1];
#pragma unroll
            for (int half = 0; half < 2; half++) {
                int rr = r + half * 8;
                float v0 = (acc[mi][ni][half * 2 + 0] + b0) * alpha;
                float v1 = (acc[mi][ni][half * 2 + 1] + b1) * alpha;
                if (epi == EPI_GELU) {
                    v0 = 0.5f * v0 * (1.0f + erff(v0 * 0.70710678118654752f));
                    v1 = 0.5f * v1 * (1.0f + erff(v1 * 0.70710678118654752f));
                } else if (epi == EPI_THETA) {
                    int l = rr & (L - 1);
                    int d0 = c & 31;
                    const float* sp = sn + l * KD + d0;
                    const float* cq = cs + l * KD + d0;
                    float s0 = sp[0], s1 = sp[1];
                    float c0 = cq[0], c1 = cq[1];
                    float o0 = v0 * c0 - v1 * s0;
                    float o1 = v1 * c1 + v0 * s1;
                    v0 = o0; v1 = o1;
                }
                if (res) {
                    v0 += res[(size_t)rr * N + c];
                    v1 += res[(size_t)rr * N + c + 1];
                }
                *(float2*)&C[(size_t)rr * N + c] = make_float2(v0, v1);
            }
        }
    }
}

__global__ __launch_bounds__(256) void gemm_kernel(
        const float* __restrict__ A, const float* __restrict__ W,
        const float* __restrict__ bias, const float* __restrict__ res,
        float* __restrict__ C, int M, int N, int K, float alpha, int epi) {
    __shared__ float As[2 * 4096];
    __shared__ float Bs[2 * 2048];
    gemm_core(A, W, bias, res, C, M, N, K, alpha, epi, nullptr, nullptr, As, Bs);
}

__global__ __launch_bounds__(256) void qkv_gemm_kernel(
        const float* __restrict__ HN,
        const float* __restrict__ wq, const float* __restrict__ wk,
        const float* __restrict__ wv,
        const float* __restrict__ bq, const float* __restrict__ bk,
        const float* __restrict__ bv,
        float* __restrict__ Qb, float* __restrict__ Kb, float* __restrict__ Vb,
        const float* __restrict__ sn, const float* __restrict__ cs) {
    __shared__ float As[2 * 4096];
    __shared__ float Bs[2 * 2048];
    int z = blockIdx.z;
    const float* W = (z == 0) ? wq : (z == 1) ? wk : wv;
    const float* bias = (z == 0) ? bq : (z == 1) ? bk : bv;
    float* C = (z == 0) ? Qb : (z == 1) ? Kb : Vb;
    float alpha = (z == 1) ? SCALING : 1.f;
    int epi = (z == 2) ? EPI_NONE : EPI_THETA;
    gemm_core(HN, W, bias, nullptr, C, Bb * L, E, E, alpha, epi, sn, cs, As, Bs);
}

__global__ __launch_bounds__(256) void ckv_gemm_kernel(
        const float* __restrict__ X, const float* __restrict__ ca_in_w,
        const float* __restrict__ ca_in_b,
        float* __restrict__ CK, float* __restrict__ CV) {
    __shared__ float As[2 * 4096];
    __shared__ float Bs[2 * 2048];
    int z = blockIdx.z;
    const float* W = ca_in_w + (size_t)(z + 1) * E * E;
    const float* bias = ca_in_b + (z + 1) * E;
    float* C = z ? CV : CK;
    gemm_core(X, W, bias, nullptr, C, Bb * L, E, E, 1.f, EPI_NONE,
              nullptr, nullptr, As, Bs);
}

// ---------------- fused dwconv3x3(+in) + LN1 --------------------------
__global__ void dwconv3_ln_kernel(const float* __restrict__ in,
                                  const float* __restrict__ w,
                                  const float* __restrict__ bias,
                                  const float* __restrict__ g,
                                  const float* __restrict__ bln,
                                  float* __restrict__ X1,
                                  float* __restrict__ HN) {
    int c = threadIdx.x;
    int wx = blockIdx.x, hy = blockIdx.y, b = blockIdx.z;
    float acc = bias[c];
#pragma unroll
    for (int kh = 0; kh < 3; kh++) {
        int y = hy + kh - 1;
        if (y < 0 || y >= HH) continue;
#pragma unroll
        for (int kw = 0; kw < 3; kw++) {
            int xx = wx + kw - 1;
            if (xx < 0 || xx >= WW) continue;
            acc += in[(((size_t)b * HH + y) * WW + xx) * E + c] *
                   w[c * 9 + kh * 3 + kw];
        }
    }
    size_t o = (((size_t)b * HH + hy) * WW + wx) * E + c;
    float v = in[o] + acc;
    X1[o] = v;
    __shared__ float s1[256], s2[256];
    s1[c] = v; s2[c] = v * v;
    __syncthreads();
    for (int off = 128; off > 0; off >>= 1) {
        if (c < off) { s1[c] += s1[c + off]; s2[c] += s2[c + off]; }
        __syncthreads();
    }
    float m = s1[0] * (1.0f / E);
    float var = s2[0] * (1.0f / E) - m * m;
    float inv = rsqrtf(var + 1e-6f);
    HN[o] = (v - m) * inv * g[c] + bln[c];
}

// ---------------- dwconv 5x5 -------------------------------------------
__global__ void dwconv5_kernel(const float* __restrict__ in,
                               const float* __restrict__ w,
                               const float* __restrict__ bias,
                               float* __restrict__ out) {
    int c = threadIdx.x;
    int wx = blockIdx.x, hy = blockIdx.y, b = blockIdx.z;
    float acc = bias[c];
#pragma unroll
    for (int kh = 0; kh < 5; kh++) {
        int y = hy + kh - 2;
        if (y < 0 || y >= HH) continue;
#pragma unroll
        for (int kw = 0; kw < 5; kw++) {
            int xx = wx + kw - 2;
            if (xx < 0 || xx >= WW) continue;
            acc += in[(((size_t)b * HH + y) * WW + xx) * E + c] *
                   w[c * 25 + kh * 5 + kw];
        }
    }
    out[(((size_t)b * HH + hy) * WW + wx) * E + c] = acc;
}

// ---------------- layernorm --------------------------------------------
__global__ void ln_kernel(const float* __restrict__ in,
                          const float* __restrict__ g,
                          const float* __restrict__ b,
                          float* __restrict__ out) {
    int row = blockIdx.x;
    int t = threadIdx.x;
    float v = in[(size_t)row * E + t];
    __shared__ float s1[256], s2[256];
    s1[t] = v; s2[t] = v * v;
    __syncthreads();
    for (int o = 128; o > 0; o >>= 1) {
        if (t < o) { s1[t] += s1[t + o]; s2[t] += s2[t + o]; }
        __syncthreads();
    }
    float m = s1[0] * (1.0f / E);
    float var = s2[0] * (1.0f / E) - m * m;
    float inv = rsqrtf(var + 1e-6f);
    out[(size_t)row * E + t] = (v - m) * inv * g[t] + b[t];
}

// ---------------- tensor-core flash attention ---------------------------
// dyn smem layout (floats): Qs[2048] | Ks[2][2048] | Vs[2][2048] | Ps[64*66]
#define PSTRIDE 66
#define ATTN_SMEM_FLOATS (2048 + 4096 + 4096 + 64 * PSTRIDE)
__global__ __launch_bounds__(128) void attn_tc_kernel(
        const float* __restrict__ Q, const float* __restrict__ Kt,
        const float* __restrict__ V, const float* __restrict__ mask,
        const float* __restrict__ addend,
        float* __restrict__ O, int Lq, int Lk, float scale) {
    extern __shared__ float sm[];
    float* Qs  = sm;
    float* KsB = sm + 2048;
    float* VsB = sm + 6144;
    float* Ps  = sm + 10240;

    int tid = threadIdx.x;
    int w = tid >> 5, lane = tid & 31;
    int lg = lane >> 2, lt = lane & 3;
    int h = blockIdx.y, b = blockIdx.z;
    int q0 = blockIdx.x * 64;
    int wm = w * 16;

    // load Q tile (64x32) via cp.async
#pragma unroll
    for (int i = 0; i < 4; i++) {
        int id = tid + 128 * i;
        int row = id >> 3, f = id & 7;
        cp16(&Qs[row * 32 + ((f ^ (row & 7)) << 2)],
             Q + ((size_t)(b * Lq + q0 + row)) * E + h * KD + f * 4);
    }

    auto loadKV = [&](int buf, int j0) {
        const float* kbase = Kt + ((size_t)(b * Lk + j0)) * E + h * KD;
        const float* vbase = V  + ((size_t)(b * Lk + j0)) * E + h * KD;
        float* Kd = KsB + buf * 2048;
        float* Vd = VsB + buf * 2048;
#pragma unroll
        for (int i = 0; i < 4; i++) {
            int id = tid + 128 * i;
            int row = id >> 3, f = id & 7;
            int dst = row * 32 + ((f ^ (row & 7)) << 2);
            cp16(&Kd[dst], kbase + (size_t)row * E + f * 4);
            cp16(&Vd[dst], vbase + (size_t)row * E + f * 4);
        }
    };

    loadKV(0, 0);
    CP_COMMIT();

    float m0 = -INFINITY, m1 = -INFINITY, l0 = 0.f, l1 = 0.f;
    float oacc[4][4] = {};
    const float* mbase = mask ? (mask + ((size_t)h * Lk + q0) * Lk) : nullptr;

    int buf = 0;
    int NJ = Lk >> 6;
    for (int jt = 0; jt < NJ; jt++) {
        int j0 = jt << 6;
        if (jt + 1 < NJ) {
            loadKV(buf ^ 1, (jt + 1) << 6);
            CP_COMMIT();
            CP_WAIT(1);
        } else {
            CP_WAIT(0);
        }
        __syncthreads();
        const float* Ks = KsB + buf * 2048;
        const float* Vs = VsB + buf * 2048;

        // S = Q @ K^T : 16x64 per warp
        float sacc[8][4];
#pragma unroll
        for (int ni = 0; ni < 8; ni++)
#pragma unroll
            for (int c = 0; c < 4; c++) sacc[ni][c] = 0.f;
#pragma unroll
        for (int kk = 0; kk < 32; kk += 8) {
            int k1 = kk + lt, k2 = k1 + 4;
            uint32_t a0 = __float_as_uint(Qs[SWIDX(wm + lg, k1)]);
            uint32_t a1 = __float_as_uint(Qs[SWIDX(wm + 8 + lg, k1)]);
            uint32_t a2 = __float_as_uint(Qs[SWIDX(wm + lg, k2)]);
            uint32_t a3 = __float_as_uint(Qs[SWIDX(wm + 8 + lg, k2)]);
#pragma unroll
            for (int ni = 0; ni < 8; ni++) {
                uint32_t b0 = __float_as_uint(Ks[SWIDX(ni * 8 + lg, k1)]);
                uint32_t b1 = __float_as_uint(Ks[SWIDX(ni * 8 + lg, k2)]);
                MMA_TF32(sacc[ni], a0, a1, a2, a3, b0, b1);
            }
        }

        // scale + mask
        if (mbase) {
            int r0 = wm + lg, r1 = wm + 8 + lg;
#pragma unroll
            for (int ni = 0; ni < 8; ni++) {
                int c = j0 + ni * 8 + lt * 2;
                float2 mv0 = *(const float2*)&mbase[(size_t)r0 * Lk + c];
                float2 mv1 = *(const float2*)&mbase[(size_t)r1 * Lk + c];
                sacc[ni][0] = sacc[ni][0] * scale + mv0.x;
                sacc[ni][1] = sacc[ni][1] * scale + mv0.y;
                sacc[ni][2] = sacc[ni][2] * scale + mv1.x;
                sacc[ni][3] = sacc[ni][3] * scale + mv1.y;
            }
        } else if (scale != 1.f) {
#pragma unroll
            for (int ni = 0; ni < 8; ni++)
#pragma unroll
                for (int c = 0; c < 4; c++) sacc[ni][c] *= scale;
        }

        // online softmax
        float rm0 = -INFINITY, rm1 = -INFINITY;
#pragma unroll
        for (int ni = 0; ni < 8; ni++) {
            rm0 = fmaxf(rm0, fmaxf(sacc[ni][0], sacc[ni][1]));
            rm1 = fmaxf(rm1, fmaxf(sacc[ni][2], sacc[ni][3]));
        }
        rm0 = fmaxf(rm0, __shfl_xor_sync(0xffffffff, rm0, 1));
        rm0 = fmaxf(rm0, __shfl_xor_sync(0xffffffff, rm0, 2));
        rm1 = fmaxf(rm1, __shfl_xor_sync(0xffffffff, rm1, 1));
        rm1 = fmaxf(rm1, __shfl_xor_sync(0xffffffff, rm1, 2));
        float mn0 = fmaxf(m0, rm0), mn1 = fmaxf(m1, rm1);
        float al0 = exp2f((m0 - mn0) * LOG2E);
        float al1 = exp2f((m1 - mn1) * LOG2E);
        float rs0 = 0.f, rs1 = 0.f;
#pragma unroll
        for (int ni = 0; ni < 8; ni++) {
            float p0 = exp2f((sacc[ni][0] - mn0) * LOG2E);
            float p1 = exp2f((sacc[ni][1] - mn0) * LOG2E);
            float p2 = exp2f((sacc[ni][2] - mn1) * LOG2E);
            float p3 = exp2f((sacc[ni][3] - mn1) * LOG2E);
            rs0 += p0 + p1; rs1 += p2 + p3;
            int c = ni * 8 + lt * 2;
            *(float2*)&Ps[(wm + lg) * PSTRIDE + c]     = make_float2(p0, p1);
            *(float2*)&Ps[(wm + 8 + lg) * PSTRIDE + c] = make_float2(p2, p3);
        }
        rs0 += __shfl_xor_sync(0xffffffff, rs0, 1);
        rs0 += __shfl_xor_sync(0xffffffff, rs0, 2);
        rs1 += __shfl_xor_sync(0xffffffff, rs1, 1);
        rs1 += __shfl_xor_sync(0xffffffff, rs1, 2);
        l0 = l0 * al0 + rs0;
        l1 = l1 * al1 + rs1;
        m0 = mn0; m1 = mn1;
#pragma unroll
        for (int ni = 0; ni < 4; ni++) {
            oacc[ni][0] *= al0; oacc[ni][1] *= al0;
            oacc[ni][2] *= al1; oacc[ni][3] *= al1;
        }
        __syncwarp();

        // O += P @ V
#pragma unroll
        for (int kk = 0; kk < 64; kk += 8) {
            int k1 = kk + lt, k2 = k1 + 4;
            uint32_t a0 = __float_as_uint(Ps[(wm + lg) * PSTRIDE + k1]);
            uint32_t a1 = __float_as_uint(Ps[(wm + 8 + lg) * PSTRIDE + k1]);
            uint32_t a2 = __float_as_uint(Ps[(wm + lg) * PSTRIDE + k2]);
            uint32_t a3 = __float_as_uint(Ps[(wm + 8 + lg) * PSTRIDE + k2]);
#pragma unroll
            for (int ni = 0; ni < 4; ni++) {
                uint32_t b0 = __float_as_uint(Vs[SWIDX(k1, ni * 8 + lg)]);
                uint32_t b1 = __float_as_uint(Vs[SWIDX(k2, ni * 8 + lg)]);
                MMA_TF32(oacc[ni], a0, a1, a2, a3, b0, b1);
            }
        }
        __syncthreads();
        buf ^= 1;
    }

    // finalize (+ optional addend, e.g. LePE)
    float inv0 = 1.f / l0, inv1 = 1.f / l1;
    int r0 = q0 + wm + lg, r1 = r0 + 8;
#pragma unroll
    for (int ni = 0; ni < 4; ni++) {
        int c = h * KD + ni * 8 + lt * 2;
        float v00 = oacc[ni][0] * inv0, v01 = oacc[ni][1] * inv0;
        float v10 = oacc[ni][2] * inv1, v11 = oacc[ni][3] * inv1;
        if (addend) {
            float2 a0 = *(const float2*)&addend[((size_t)(b * Lq + r0)) * E + c];
            float2 a1 = *(const float2*)&addend[((size_t)(b * Lq + r1)) * E + c];
            v00 += a0.x; v01 += a0.y; v10 += a1.x; v11 += a1.y;
        }
        *(float2*)&O[((size_t)(b * Lq + r0)) * E + c] = make_float2(v00, v01);
        *(float2*)&O[((size_t)(b * Lq + r1)) * E + c] = make_float2(v10, v11);
    }
}

// ---------------- launcher ----------------------------------------------
extern "C" void kernel_launch(void* const* d_in, const int* in_sizes, int n_in,
                              void* d_out, int out_size) {
    const float* x       = (const float*)d_in[0];
    const float* queries = (const float*)d_in[1];
    const float* sn      = (const float*)d_in[2];
    const float* cs      = (const float*)d_in[3];
    const float* mask    = (const float*)d_in[4];
    const float* ln1_g   = (const float*)d_in[5];
    const float* ln1_b   = (const float*)d_in[6];
    const float* ln2_g   = (const float*)d_in[7];
    const float* ln2_b   = (const float*)d_in[8];
    const float* wq      = (const float*)d_in[9];
    const float* bq      = (const float*)d_in[10];
    const float* wk      = (const float*)d_in[11];
    const float* bk      = (const float*)d_in[12];
    const float* wv      = (const float*)d_in[13];
    const float* bv      = (const float*)d_in[14];
    const float* lepe_w  = (const float*)d_in[15];
    const float* lepe_b  = (const float*)d_in[16];
    const float* wo      = (const float*)d_in[17];
    const float* bo      = (const float*)d_in[18];
    const float* fc1_w   = (const float*)d_in[19];
    const float* fc1_b   = (const float*)d_in[20];
    const float* fc2_w   = (const float*)d_in[21];
    const float* fc2_b   = (const float*)d_in[22];
    const float* pos_w   = (const float*)d_in[23];
    const float* pos_b   = (const float*)d_in[24];
    const float* ca_in_w = (const float*)d_in[25];
    const float* ca_in_b = (const float*)d_in[26];
    const float* ca_out_w= (const float*)d_in[27];
    const float* ca_out_b= (const float*)d_in[28];

    void* sp = nullptr;
    cudaGetSymbolAddress(&sp, g_scratch);
    float* S = (float*)sp;
    float* X1   = S + OFF_X1;
    float* HN   = S + OFF_HN;
    float* Qb   = S + OFF_Q;
    float* Kb   = S + OFF_K;
    float* Vb   = S + OFF_V;
    float* LEPE = S + OFF_LEPE;
    float* AO   = S + OFF_AO;
    float* X2   = S + OFF_X2;
    float* FF   = S + OFF_FF;
    float* CK   = S + OFF_CK;
    float* CV   = S + OFF_CV;
    float* CQ   = S + OFF_CQ;
    float* CAO  = S + OFF_CAO;
    float* Q2   = S + OFF_Q2;
    float* QLN  = S + OFF_QLN;
    float* QLN2 = S + OFF_QLN2;
    float* QFF  = S + OFF_QFF;

    float* OX = (float*)d_out;
    float* OQ = OX + (size_t)Bb * L * E;

    const int MTOK = Bb * L;   // 8192
    const int MQ   = Bb * NQ;  // 512
    dim3 sp3(WW, HH, Bb);
    const int ATTN_SMEM = ATTN_SMEM_FLOATS * 4;
    static bool attr_set = false;
    if (!attr_set) {
        cudaFuncSetAttribute(attn_tc_kernel,
                             cudaFuncAttributeMaxDynamicSharedMemorySize,
                             ATTN_SMEM);
        attr_set = true;
    }

    // 1. x1 = x + dwconv3(x); hn = LN1(x1)   (fused)
    dwconv3_ln_kernel<<<sp3, 256>>>(x, pos_w, pos_b, ln1_g, ln1_b, X1, HN);
    // 2. q(theta), k(theta, *scaling), v — one batched launch
    qkv_gemm_kernel<<<dim3(E/64, MTOK/128, 3), 256>>>(
        HN, wq, wk, wv, bq, bk, bv, Qb, Kb, Vb, sn, cs);
    // 3. lepe = dwconv5(v)
    dwconv5_kernel<<<sp3, 256>>>(Vb, lepe_w, lepe_b, LEPE);
    // 4. self attention + lepe add
    attn_tc_kernel<<<dim3(L/64, HEADS, Bb), 128, ATTN_SMEM>>>(
        Qb, Kb, Vb, mask, LEPE, AO, L, L, 1.f);
    // 5. x2 = x1 + ao @ wo^T + bo
    gemm_kernel<<<dim3(E/64, MTOK/128), 256>>>(AO, wo, bo, X1, X2, MTOK, E, E, 1.f, EPI_NONE);
    // 6. FFN on x
    ln_kernel<<<MTOK, 256>>>(X2, ln2_g, ln2_b, HN);
    gemm_kernel<<<dim3(FFN/64, MTOK/128), 256>>>(HN, fc1_w, fc1_b, nullptr, FF, MTOK, FFN, E, 1.f, EPI_GELU);
    gemm_kernel<<<dim3(E/64, MTOK/128), 256>>>(FF, fc2_w, fc2_b, X2, OX, MTOK, E, FFN, 1.f, EPI_NONE);
    // 7. cross attention
    ln_kernel<<<MQ, 256>>>(queries, ln1_g, ln1_b, QLN);
    gemm_kernel<<<dim3(E/64, MQ/128), 256>>>(QLN, ca_in_w, ca_in_b, nullptr, CQ, MQ, E, E, 1.f, EPI_NONE);
    ckv_gemm_kernel<<<dim3(E/64, MTOK/128, 2), 256>>>(OX, ca_in_w, ca_in_b, CK, CV);
    attn_tc_kernel<<<dim3(NQ/64, HEADS, Bb), 128, ATTN_SMEM>>>(
        CQ, CK, CV, nullptr, nullptr, CAO, NQ, L, SCALING);
    gemm_kernel<<<dim3(E/64, MQ/128), 256>>>(CAO, ca_out_w, ca_out_b, queries, Q2, MQ, E, E, 1.f, EPI_NONE);
    // 8. FFN on queries
    ln_kernel<<<MQ, 256>>>(Q2, ln2_g, ln2_b, QLN2);
    gemm_kernel<<<dim3(FFN/64, MQ/128), 256>>>(QLN2, fc1_w, fc1_b, nullptr, QFF, MQ, FFN, E, 1.f, EPI_GELU);
    gemm_kernel<<<dim3(E/64, MQ/128), 256>>>(QFF, fc2_w, fc2_b, Q2, OQ, MQ, E, FFN, 1.f, EPI_NONE);
}

// round 5
// speedup vs baseline: 4.2919x; 1.1825x over previous
#include <cuda_runtime.h>
#include <cuda_bf16.h>
#include <math.h>
#include <stdint.h>

#define Bb 8
#define HH 32
#define WW 32
#define E 256
#define HEADS 8
#define KD 32
#define FFN 1024
#define NQ 64
#define L 1024
#define SCALING 0.17677669529663687f
#define LOG2E 1.4426950408889634f

#define EPI_NONE 0
#define EPI_GELU 1
#define EPI_THETA 2

// ---------------- scratch arena ----------------
#define SZ_TOK (Bb * L * E)
#define SZ_QTK (Bb * NQ * E)
#define OFF_X1   ((size_t)0)
#define OFF_HN   (OFF_X1   + SZ_TOK)
#define OFF_V    (OFF_HN   + SZ_TOK)
#define OFF_LEPE (OFF_V    + SZ_TOK)
#define OFF_AO   (OFF_LEPE + SZ_TOK)
#define OFF_X2   (OFF_AO   + SZ_TOK)
#define OFF_FF   (OFF_X2   + SZ_TOK)
#define OFF_CAO  (OFF_FF   + (size_t)Bb * L * FFN)
#define OFF_Q2   (OFF_CAO  + SZ_QTK)
#define OFF_QLN  (OFF_Q2   + SZ_QTK)
#define OFF_QLN2 (OFF_QLN  + SZ_QTK)
#define OFF_QFF  (OFF_QLN2 + SZ_QTK)
// bf16 buffers (sizes in float units = elems/2)
#define OFF_QH   (OFF_QFF  + (size_t)Bb * NQ * FFN)
#define OFF_KH   (OFF_QH   + SZ_TOK / 2)
#define OFF_VH   (OFF_KH   + SZ_TOK / 2)
#define OFF_CKH  (OFF_VH   + SZ_TOK / 2)
#define OFF_CVH  (OFF_CKH  + SZ_TOK / 2)
#define OFF_CQH  (OFF_CVH  + SZ_TOK / 2)
#define SCRATCH_TOTAL (OFF_CQH + SZ_QTK / 2)

__device__ float g_scratch[SCRATCH_TOTAL];

// ---------------- async copy / ldsm / mma helpers ----------------
__device__ __forceinline__ void cp16(void* dst, const void* src) {
    uint32_t d = (uint32_t)__cvta_generic_to_shared(dst);
    asm volatile("cp.async.cg.shared.global [%0], [%1], 16;" :: "r"(d), "l"(src));
}
#define CP_COMMIT() asm volatile("cp.async.commit_group;" ::: "memory")
#define CP_WAIT(N)  asm volatile("cp.async.wait_group %0;" :: "n"(N) : "memory")

__device__ __forceinline__ uint32_t saddr(const void* p) {
    return (uint32_t)__cvta_generic_to_shared(p);
}

#define LDSM_X4(r0, r1, r2, r3, a)                                          \
    asm volatile("ldmatrix.sync.aligned.m8n8.x4.shared.b16 {%0,%1,%2,%3}, [%4];" \
        : "=r"(r0), "=r"(r1), "=r"(r2), "=r"(r3) : "r"(a))
#define LDSM_X4T(r0, r1, r2, r3, a)                                         \
    asm volatile("ldmatrix.sync.aligned.m8n8.x4.trans.shared.b16 {%0,%1,%2,%3}, [%4];" \
        : "=r"(r0), "=r"(r1), "=r"(r2), "=r"(r3) : "r"(a))

#define MMA_TF32(acc, a0, a1, a2, a3, b0, b1)                               \
    asm volatile(                                                           \
        "mma.sync.aligned.m16n8k8.row.col.f32.tf32.tf32.f32 "               \
        "{%0,%1,%2,%3}, {%4,%5,%6,%7}, {%8,%9}, {%0,%1,%2,%3};"             \
        : "+f"(acc[0]), "+f"(acc[1]), "+f"(acc[2]), "+f"(acc[3])            \
        : "r"(a0), "r"(a1), "r"(a2), "r"(a3), "r"(b0), "r"(b1))

#define MMA_BF16(acc, a0, a1, a2, a3, b0, b1)                               \
    asm volatile(                                                           \
        "mma.sync.aligned.m16n8k16.row.col.f32.bf16.bf16.f32 "              \
        "{%0,%1,%2,%3}, {%4,%5,%6,%7}, {%8,%9}, {%0,%1,%2,%3};"             \
        : "+f"(acc[0]), "+f"(acc[1]), "+f"(acc[2]), "+f"(acc[3])            \
        : "r"(a0), "r"(a1), "r"(a2), "r"(a3), "r"(b0), "r"(b1))

#define SWIDX(r, k) (((r) << 5) + (((((k) >> 2) ^ ((r) & 7))) << 2) + ((k) & 3))

// ---------------- GEMM core: tf32, outputs fp32 and/or bf16 --------------
__device__ __forceinline__ void gemm_core(
        const float* __restrict__ A, const float* __restrict__ W,
        const float* __restrict__ bias, const float* __restrict__ res,
        float* __restrict__ C, __nv_bfloat16* __restrict__ Ch,
        int M, int N, int K, float alpha, int epi,
        const float* __restrict__ sn, const float* __restrict__ cs,
        float* As, float* Bs) {
    int tid = threadIdx.x;
    int w = tid >> 5, lane = tid & 31;
    int wm = (w & 3) * 32, wn = (w >> 2) * 32;
    int m0 = blockIdx.y * 128, n0 = blockIdx.x * 64;
    int lg = lane >> 2, lt = lane & 3;

    float acc[2][4][4] = {};

    auto loadTile = [&](int buf, int k0) {
        float* Ab = As + buf * 4096;
        float* Bd = Bs + buf * 2048;
#pragma unroll
        for (int i = 0; i < 4; i++) {
            int id = tid + 256 * i;
            int row = id >> 3, f = id & 7;
            cp16(&Ab[row * 32 + ((f ^ (row & 7)) << 2)],
                 &A[(size_t)(m0 + row) * K + k0 + f * 4]);
        }
#pragma unroll
        for (int i = 0; i < 2; i++) {
            int id = tid + 256 * i;
            int row = id >> 3, f = id & 7;
            cp16(&Bd[row * 32 + ((f ^ (row & 7)) << 2)],
                 &W[(size_t)(n0 + row) * K + k0 + f * 4]);
        }
    };

    int KT = K >> 5;
    int buf = 0;
    loadTile(0, 0);
    CP_COMMIT();
    for (int kt = 0; kt < KT; kt++) {
        if (kt + 1 < KT) {
            loadTile(buf ^ 1, (kt + 1) << 5);
            CP_COMMIT();
            CP_WAIT(1);
        } else {
            CP_WAIT(0);
        }
        __syncthreads();
        const float* Ab = As + buf * 4096;
        const float* Bd = Bs + buf * 2048;
#pragma unroll
        for (int kk = 0; kk < 32; kk += 8) {
            int k1 = kk + lt, k2 = k1 + 4;
            uint32_t af[2][4];
#pragma unroll
            for (int mi = 0; mi < 2; mi++) {
                int r = wm + mi * 16 + lg;
                af[mi][0] = __float_as_uint(Ab[SWIDX(r, k1)]);
                af[mi][1] = __float_as_uint(Ab[SWIDX(r + 8, k1)]);
                af[mi][2] = __float_as_uint(Ab[SWIDX(r, k2)]);
                af[mi][3] = __float_as_uint(Ab[SWIDX(r + 8, k2)]);
            }
            uint32_t bf[4][2];
#pragma unroll
            for (int ni = 0; ni < 4; ni++) {
                int c = wn + ni * 8 + lg;
                bf[ni][0] = __float_as_uint(Bd[SWIDX(c, k1)]);
                bf[ni][1] = __float_as_uint(Bd[SWIDX(c, k2)]);
            }
#pragma unroll
            for (int mi = 0; mi < 2; mi++)
#pragma unroll
                for (int ni = 0; ni < 4; ni++)
                    MMA_TF32(acc[mi][ni], af[mi][0], af[mi][1], af[mi][2],
                             af[mi][3], bf[ni][0], bf[ni][1]);
        }
        __syncthreads();
        buf ^= 1;
    }

#pragma unroll
    for (int mi = 0; mi < 2; mi++) {
#pragma unroll
        for (int ni = 0; ni < 4; ni++) {
            int r = m0 + wm + mi * 16 + lg;
            int c = n0 + wn + ni * 8 + lt * 2;
            float b0 = bias[c], b1 = bias[c + 1];
#pragma unroll
            for (int half = 0; half < 2; half++) {
                int rr = r + half * 8;
                float v0 = (acc[mi][ni][half * 2 + 0] + b0) * alpha;
                float v1 = (acc[mi][ni][half * 2 + 1] + b1) * alpha;
                if (epi == EPI_GELU) {
                    v0 = 0.5f * v0 * (1.0f + erff(v0 * 0.70710678118654752f));
                    v1 = 0.5f * v1 * (1.0f + erff(v1 * 0.70710678118654752f));
                } else if (epi == EPI_THETA) {
                    int l = rr & (L - 1);
                    int d0 = c & 31;
                    const float* sp = sn + l * KD + d0;
                    const float* cq = cs + l * KD + d0;
                    float s0 = sp[0], s1 = sp[1];
                    float c0 = cq[0], c1 = cq[1];
                    float o0 = v0 * c0 - v1 * s0;
                    float o1 = v1 * c1 + v0 * s1;
                    v0 = o0; v1 = o1;
                }
                if (res) {
                    v0 += res[(size_t)rr * N + c];
                    v1 += res[(size_t)rr * N + c + 1];
                }
                if (C)
                    *(float2*)&C[(size_t)rr * N + c] = make_float2(v0, v1);
                if (Ch) {
                    __nv_bfloat162 hv = __floats2bfloat162_rn(v0, v1);
                    *(__nv_bfloat162*)&Ch[(size_t)rr * N + c] = hv;
                }
            }
        }
    }
}

__global__ __launch_bounds__(256) void gemm_kernel(
        const float* __restrict__ A, const float* __restrict__ W,
        const float* __restrict__ bias, const float* __restrict__ res,
        float* __restrict__ C, __nv_bfloat16* __restrict__ Ch,
        int M, int N, int K, float alpha, int epi) {
    __shared__ float As[2 * 4096];
    __shared__ float Bs[2 * 2048];
    gemm_core(A, W, bias, res, C, Ch, M, N, K, alpha, epi, nullptr, nullptr, As, Bs);
}

__global__ __launch_bounds__(256) void qkv_gemm_kernel(
        const float* __restrict__ HN,
        const float* __restrict__ wq, const float* __restrict__ wk,
        const float* __restrict__ wv,
        const float* __restrict__ bq, const float* __restrict__ bk,
        const float* __restrict__ bv,
        __nv_bfloat16* __restrict__ QH, __nv_bfloat16* __restrict__ KH,
        float* __restrict__ Vb, __nv_bfloat16* __restrict__ VH,
        const float* __restrict__ sn, const float* __restrict__ cs) {
    __shared__ float As[2 * 4096];
    __shared__ float Bs[2 * 2048];
    int z = blockIdx.z;
    const float* W = (z == 0) ? wq : (z == 1) ? wk : wv;
    const float* bias = (z == 0) ? bq : (z == 1) ? bk : bv;
    float* C = (z == 2) ? Vb : nullptr;
    __nv_bfloat16* Ch = (z == 0) ? QH : (z == 1) ? KH : VH;
    float alpha = (z == 1) ? SCALING : 1.f;
    int epi = (z == 2) ? EPI_NONE : EPI_THETA;
    gemm_core(HN, W, bias, nullptr, C, Ch, Bb * L, E, E, alpha, epi, sn, cs, As, Bs);
}

__global__ __launch_bounds__(256) void ckv_gemm_kernel(
        const float* __restrict__ X, const float* __restrict__ ca_in_w,
        const float* __restrict__ ca_in_b,
        __nv_bfloat16* __restrict__ CKH, __nv_bfloat16* __restrict__ CVH) {
    __shared__ float As[2 * 4096];
    __shared__ float Bs[2 * 2048];
    int z = blockIdx.z;
    const float* W = ca_in_w + (size_t)(z + 1) * E * E;
    const float* bias = ca_in_b + (z + 1) * E;
    __nv_bfloat16* Ch = z ? CVH : CKH;
    gemm_core(X, W, bias, nullptr, nullptr, Ch, Bb * L, E, E, 1.f, EPI_NONE,
              nullptr, nullptr, As, Bs);
}

// ---------------- fused dwconv3x3(+in) + LN1 --------------------------
__global__ void dwconv3_ln_kernel(const float* __restrict__ in,
                                  const float* __restrict__ w,
                                  const float* __restrict__ bias,
                                  const float* __restrict__ g,
                                  const float* __restrict__ bln,
                                  float* __restrict__ X1,
                                  float* __restrict__ HN) {
    int c = threadIdx.x;
    int wx = blockIdx.x, hy = blockIdx.y, b = blockIdx.z;
    float acc = bias[c];
#pragma unroll
    for (int kh = 0; kh < 3; kh++) {
        int y = hy + kh - 1;
        if (y < 0 || y >= HH) continue;
#pragma unroll
        for (int kw = 0; kw < 3; kw++) {
            int xx = wx + kw - 1;
            if (xx < 0 || xx >= WW) continue;
            acc += in[(((size_t)b * HH + y) * WW + xx) * E + c] *
                   w[c * 9 + kh * 3 + kw];
        }
    }
    size_t o = (((size_t)b * HH + hy) * WW + wx) * E + c;
    float v = in[o] + acc;
    X1[o] = v;
    __shared__ float s1[256], s2[256];
    s1[c] = v; s2[c] = v * v;
    __syncthreads();
    for (int off = 128; off > 0; off >>= 1) {
        if (c < off) { s1[c] += s1[c + off]; s2[c] += s2[c + off]; }
        __syncthreads();
    }
    float m = s1[0] * (1.0f / E);
    float var = s2[0] * (1.0f / E) - m * m;
    float inv = rsqrtf(var + 1e-6f);
    HN[o] = (v - m) * inv * g[c] + bln[c];
}

// ---------------- dwconv 5x5 -------------------------------------------
__global__ void dwconv5_kernel(const float* __restrict__ in,
                               const float* __restrict__ w,
                               const float* __restrict__ bias,
                               float* __restrict__ out) {
    int c = threadIdx.x;
    int wx = blockIdx.x, hy = blockIdx.y, b = blockIdx.z;
    float acc = bias[c];
#pragma unroll
    for (int kh = 0; kh < 5; kh++) {
        int y = hy + kh - 2;
        if (y < 0 || y >= HH) continue;
#pragma unroll
        for (int kw = 0; kw < 5; kw++) {
            int xx = wx + kw - 2;
            if (xx < 0 || xx >= WW) continue;
            acc += in[(((size_t)b * HH + y) * WW + xx) * E + c] *
                   w[c * 25 + kh * 5 + kw];
        }
    }
    out[(((size_t)b * HH + hy) * WW + wx) * E + c] = acc;
}

// ---------------- layernorm --------------------------------------------
__global__ void ln_kernel(const float* __restrict__ in,
                          const float* __restrict__ g,
                          const float* __restrict__ b,
                          float* __restrict__ out) {
    int row = blockIdx.x;
    int t = threadIdx.x;
    float v = in[(size_t)row * E + t];
    __shared__ float s1[256], s2[256];
    s1[t] = v; s2[t] = v * v;
    __syncthreads();
    for (int o = 128; o > 0; o >>= 1) {
        if (t < o) { s1[t] += s1[t + o]; s2[t] += s2[t + o]; }
        __syncthreads();
    }
    float m = s1[0] * (1.0f / E);
    float var = s2[0] * (1.0f / E) - m * m;
    float inv = rsqrtf(var + 1e-6f);
    out[(size_t)row * E + t] = (v - m) * inv * g[t] + b[t];
}

// ---------------- bf16 tensor-core flash attention -----------------------
// One block per (64-query tile, head, batch), 4 warps x 16 rows.
// K/V staged bf16 via cp.async (double buffered), fragments via ldmatrix.
// KV/Q tiles: 64 rows x 40 bf16 (80B stride). P tile: 64 x 72 bf16 (144B).
#define KVS 40
#define PSS 72
__global__ __launch_bounds__(128) void attn_bf16_kernel(
        const __nv_bfloat16* __restrict__ Q,
        const __nv_bfloat16* __restrict__ Kt,
        const __nv_bfloat16* __restrict__ V,
        const float* __restrict__ mask, const float* __restrict__ addend,
        float* __restrict__ O, int Lq, int Lk, float scale) {
    __shared__ __align__(16) __nv_bfloat16 Qs[64 * KVS];
    __shared__ __align__(16) __nv_bfloat16 Ks[2][64 * KVS];
    __shared__ __align__(16) __nv_bfloat16 Vs[2][64 * KVS];
    __shared__ __align__(16) __nv_bfloat16 Ps[64 * PSS];

    int tid = threadIdx.x;
    int w = tid >> 5, lane = tid & 31;
    int lg = lane >> 2, lt = lane & 3;
    int h = blockIdx.y, b = blockIdx.z;
    int q0 = blockIdx.x * 64;
    int wm = w * 16;

    // ldmatrix per-lane row/col offsets (x4 pattern)
    int ldrow = (lane & 7) + ((lane >> 3) & 1) * 8;
    int ldcol = (lane >> 4) * 8;

    auto loadTile = [&](__nv_bfloat16* dst, const __nv_bfloat16* src) {
#pragma unroll
        for (int i = 0; i < 2; i++) {
            int id = tid + 128 * i;
            int row = id >> 2, gr = id & 3;
            cp16(dst + row * KVS + gr * 8, src + (size_t)row * E + gr * 8);
        }
    };

    const __nv_bfloat16* qbase = Q + ((size_t)(b * Lq + q0)) * E + h * KD;
    loadTile(Qs, qbase);
    CP_COMMIT();
    loadTile(Ks[0], Kt + ((size_t)(b * Lk)) * E + h * KD);
    loadTile(Vs[0], V + ((size_t)(b * Lk)) * E + h * KD);
    CP_COMMIT();
    CP_WAIT(1);
    __syncthreads();

    // hoist Q fragments (2 k-steps of 16)
    uint32_t qf[2][4];
#pragma unroll
    for (int ks = 0; ks < 2; ks++)
        LDSM_X4(qf[ks][0], qf[ks][1], qf[ks][2], qf[ks][3],
                saddr(&Qs[(wm + ldrow) * KVS + ks * 16 + ldcol]));

    float m0 = -INFINITY, m1 = -INFINITY, l0 = 0.f, l1 = 0.f;
    float oacc[4][4] = {};
    const float* mbase = mask ? (mask + ((size_t)h * Lk + q0) * Lk) : nullptr;

    int buf = 0;
    int NJ = Lk >> 6;
    for (int jt = 0; jt < NJ; jt++) {
        int j0 = jt << 6;
        if (jt + 1 < NJ) {
            const __nv_bfloat16* kb = Kt + ((size_t)(b * Lk + j0 + 64)) * E + h * KD;
            const __nv_bfloat16* vb = V  + ((size_t)(b * Lk + j0 + 64)) * E + h * KD;
            loadTile(Ks[buf ^ 1], kb);
            loadTile(Vs[buf ^ 1], vb);
            CP_COMMIT();
            CP_WAIT(1);
        } else {
            CP_WAIT(0);
        }
        __syncthreads();

        // preload mask values
        float2 mv[8][2];
        if (mbase) {
            int r0 = wm + lg, r1 = wm + 8 + lg;
#pragma unroll
            for (int ni = 0; ni < 8; ni++) {
                int c = j0 + ni * 8 + lt * 2;
                mv[ni][0] = *(const float2*)&mbase[(size_t)r0 * Lk + c];
                mv[ni][1] = *(const float2*)&mbase[(size_t)r1 * Lk + c];
            }
        }

        // S = Q @ K^T : 16x64 per warp
        float sacc[8][4];
#pragma unroll
        for (int ni = 0; ni < 8; ni++)
#pragma unroll
            for (int c = 0; c < 4; c++) sacc[ni][c] = 0.f;
#pragma unroll
        for (int ks = 0; ks < 2; ks++) {
#pragma unroll
            for (int nb = 0; nb < 4; nb++) {
                uint32_t r0, r1, r2, r3;
                LDSM_X4(r0, r1, r2, r3,
                        saddr(&Ks[buf][(nb * 16 + ldrow) * KVS + ks * 16 + ldcol]));
                MMA_BF16(sacc[2 * nb],     qf[ks][0], qf[ks][1], qf[ks][2], qf[ks][3], r0, r2);
                MMA_BF16(sacc[2 * nb + 1], qf[ks][0], qf[ks][1], qf[ks][2], qf[ks][3], r1, r3);
            }
        }

        // scale + mask
        if (mbase) {
#pragma unroll
            for (int ni = 0; ni < 8; ni++) {
                sacc[ni][0] = sacc[ni][0] * scale + mv[ni][0].x;
                sacc[ni][1] = sacc[ni][1] * scale + mv[ni][0].y;
                sacc[ni][2] = sacc[ni][2] * scale + mv[ni][1].x;
                sacc[ni][3] = sacc[ni][3] * scale + mv[ni][1].y;
            }
        } else if (scale != 1.f) {
#pragma unroll
            for (int ni = 0; ni < 8; ni++)
#pragma unroll
                for (int c = 0; c < 4; c++) sacc[ni][c] *= scale;
        }

        // online softmax
        float rm0 = -INFINITY, rm1 = -INFINITY;
#pragma unroll
        for (int ni = 0; ni < 8; ni++) {
            rm0 = fmaxf(rm0, fmaxf(sacc[ni][0], sacc[ni][1]));
            rm1 = fmaxf(rm1, fmaxf(sacc[ni][2], sacc[ni][3]));
        }
        rm0 = fmaxf(rm0, __shfl_xor_sync(0xffffffff, rm0, 1));
        rm0 = fmaxf(rm0, __shfl_xor_sync(0xffffffff, rm0, 2));
        rm1 = fmaxf(rm1, __shfl_xor_sync(0xffffffff, rm1, 1));
        rm1 = fmaxf(rm1, __shfl_xor_sync(0xffffffff, rm1, 2));
        float mn0 = fmaxf(m0, rm0), mn1 = fmaxf(m1, rm1);
        float al0 = exp2f((m0 - mn0) * LOG2E);
        float al1 = exp2f((m1 - mn1) * LOG2E);
        float rs0 = 0.f, rs1 = 0.f;
#pragma unroll
        for (int ni = 0; ni < 8; ni++) {
            float p0 = exp2f((sacc[ni][0] - mn0) * LOG2E);
            float p1 = exp2f((sacc[ni][1] - mn0) * LOG2E);
            float p2 = exp2f((sacc[ni][2] - mn1) * LOG2E);
            float p3 = exp2f((sacc[ni][3] - mn1) * LOG2E);
            rs0 += p0 + p1; rs1 += p2 + p3;
            int c = ni * 8 + lt * 2;
            __nv_bfloat162 plo = __floats2bfloat162_rn(p0, p1);
            __nv_bfloat162 phi = __floats2bfloat162_rn(p2, p3);
            *(__nv_bfloat162*)&Ps[(wm + lg) * PSS + c]     = plo;
            *(__nv_bfloat162*)&Ps[(wm + 8 + lg) * PSS + c] = phi;
        }
        rs0 += __shfl_xor_sync(0xffffffff, rs0, 1);
        rs0 += __shfl_xor_sync(0xffffffff, rs0, 2);
        rs1 += __shfl_xor_sync(0xffffffff, rs1, 1);
        rs1 += __shfl_xor_sync(0xffffffff, rs1, 2);
        l0 = l0 * al0 + rs0;
        l1 = l1 * al1 + rs1;
        m0 = mn0; m1 = mn1;
#pragma unroll
        for (int ni = 0; ni < 4; ni++) {
            oacc[ni][0] *= al0; oacc[ni][1] *= al0;
            oacc[ni][2] *= al1; oacc[ni][3] *= al1;
        }
        __syncwarp();

        // O += P @ V
#pragma unroll
        for (int ks = 0; ks < 4; ks++) {
            uint32_t pa0, pa1, pa2, pa3;
            LDSM_X4(pa0, pa1, pa2, pa3,
                    saddr(&Ps[(wm + ldrow) * PSS + ks * 16 + ldcol]));
            uint32_t v0, v1, v2, v3;
            LDSM_X4T(v0, v1, v2, v3,
                     saddr(&Vs[buf][(ks * 16 + ldrow) * KVS + 0 + ldcol]));
            uint32_t u0, u1, u2, u3;
            LDSM_X4T(u0, u1, u2, u3,
                     saddr(&Vs[buf][(ks * 16 + ldrow) * KVS + 16 + ldcol]));
            MMA_BF16(oacc[0], pa0, pa1, pa2, pa3, v0, v1);
            MMA_BF16(oacc[1], pa0, pa1, pa2, pa3, v2, v3);
            MMA_BF16(oacc[2], pa0, pa1, pa2, pa3, u0, u1);
            MMA_BF16(oacc[3], pa0, pa1, pa2, pa3, u2, u3);
        }
        __syncthreads();
        buf ^= 1;
    }

    // finalize (+ optional addend, e.g. LePE)
    float inv0 = 1.f / l0, inv1 = 1.f / l1;
    int r0 = q0 + wm + lg, r1 = r0 + 8;
#pragma unroll
    for (int ni = 0; ni < 4; ni++) {
        int c = h * KD + ni * 8 + lt * 2;
        float v00 = oacc[ni][0] * inv0, v01 = oacc[ni][1] * inv0;
        float v10 = oacc[ni][2] * inv1, v11 = oacc[ni][3] * inv1;
        if (addend) {
            float2 a0 = *(const float2*)&addend[((size_t)(b * Lq + r0)) * E + c];
            float2 a1 = *(const float2*)&addend[((size_t)(b * Lq + r1)) * E + c];
            v00 += a0.x; v01 += a0.y; v10 += a1.x; v11 += a1.y;
        }
        *(float2*)&O[((size_t)(b * Lq + r0)) * E + c] = make_float2(v00, v01);
        *(float2*)&O[((size_t)(b * Lq + r1)) * E + c] = make_float2(v10, v11);
    }
}

// ---------------- launcher ----------------------------------------------
extern "C" void kernel_launch(void* const* d_in, const int* in_sizes, int n_in,
                              void* d_out, int out_size) {
    const float* x       = (const float*)d_in[0];
    const float* queries = (const float*)d_in[1];
    const float* sn      = (const float*)d_in[2];
    const float* cs      = (const float*)d_in[3];
    const float* mask    = (const float*)d_in[4];
    const float* ln1_g   = (const float*)d_in[5];
    const float* ln1_b   = (const float*)d_in[6];
    const float* ln2_g   = (const float*)d_in[7];
    const float* ln2_b   = (const float*)d_in[8];
    const float* wq      = (const float*)d_in[9];
    const float* bq      = (const float*)d_in[10];
    const float* wk      = (const float*)d_in[11];
    const float* bk      = (const float*)d_in[12];
    const float* wv      = (const float*)d_in[13];
    const float* bv      = (const float*)d_in[14];
    const float* lepe_w  = (const float*)d_in[15];
    const float* lepe_b  = (const float*)d_in[16];
    const float* wo      = (const float*)d_in[17];
    const float* bo      = (const float*)d_in[18];
    const float* fc1_w   = (const float*)d_in[19];
    const float* fc1_b   = (const float*)d_in[20];
    const float* fc2_w   = (const float*)d_in[21];
    const float* fc2_b   = (const float*)d_in[22];
    const float* pos_w   = (const float*)d_in[23];
    const float* pos_b   = (const float*)d_in[24];
    const float* ca_in_w = (const float*)d_in[25];
    const float* ca_in_b = (const float*)d_in[26];
    const float* ca_out_w= (const float*)d_in[27];
    const float* ca_out_b= (const float*)d_in[28];

    void* sp = nullptr;
    cudaGetSymbolAddress(&sp, g_scratch);
    float* S = (float*)sp;
    float* X1   = S + OFF_X1;
    float* HN   = S + OFF_HN;
    float* Vb   = S + OFF_V;
    float* LEPE = S + OFF_LEPE;
    float* AO   = S + OFF_AO;
    float* X2   = S + OFF_X2;
    float* FF   = S + OFF_FF;
    float* CAO  = S + OFF_CAO;
    float* Q2   = S + OFF_Q2;
    float* QLN  = S + OFF_QLN;
    float* QLN2 = S + OFF_QLN2;
    float* QFF  = S + OFF_QFF;
    __nv_bfloat16* QH  = (__nv_bfloat16*)(S + OFF_QH);
    __nv_bfloat16* KH  = (__nv_bfloat16*)(S + OFF_KH);
    __nv_bfloat16* VH  = (__nv_bfloat16*)(S + OFF_VH);
    __nv_bfloat16* CKH = (__nv_bfloat16*)(S + OFF_CKH);
    __nv_bfloat16* CVH = (__nv_bfloat16*)(S + OFF_CVH);
    __nv_bfloat16* CQH = (__nv_bfloat16*)(S + OFF_CQH);

    float* OX = (float*)d_out;
    float* OQ = OX + (size_t)Bb * L * E;

    const int MTOK = Bb * L;   // 8192
    const int MQ   = Bb * NQ;  // 512
    dim3 sp3(WW, HH, Bb);

    // 1. x1 = x + dwconv3(x); hn = LN1(x1)
    dwconv3_ln_kernel<<<sp3, 256>>>(x, pos_w, pos_b, ln1_g, ln1_b, X1, HN);
    // 2. q(theta) -> bf16, k(theta, *scaling) -> bf16, v -> fp32 + bf16
    qkv_gemm_kernel<<<dim3(E/64, MTOK/128, 3), 256>>>(
        HN, wq, wk, wv, bq, bk, bv, QH, KH, Vb, VH, sn, cs);
    // 3. lepe = dwconv5(v)
    dwconv5_kernel<<<sp3, 256>>>(Vb, lepe_w, lepe_b, LEPE);
    // 4. self attention (bf16 tensor cores) + lepe add
    attn_bf16_kernel<<<dim3(L/64, HEADS, Bb), 128>>>(
        QH, KH, VH, mask, LEPE, AO, L, L, 1.f);
    // 5. x2 = x1 + ao @ wo^T + bo
    gemm_kernel<<<dim3(E/64, MTOK/128), 256>>>(AO, wo, bo, X1, X2, nullptr, MTOK, E, E, 1.f, EPI_NONE);
    // 6. FFN on x
    ln_kernel<<<MTOK, 256>>>(X2, ln2_g, ln2_b, HN);
    gemm_kernel<<<dim3(FFN/64, MTOK/128), 256>>>(HN, fc1_w, fc1_b, nullptr, FF, nullptr, MTOK, FFN, E, 1.f, EPI_GELU);
    gemm_kernel<<<dim3(E/64, MTOK/128), 256>>>(FF, fc2_w, fc2_b, X2, OX, nullptr, MTOK, E, FFN, 1.f, EPI_NONE);
    // 7. cross attention
    ln_kernel<<<MQ, 256>>>(queries, ln1_g, ln1_b, QLN);
    gemm_kernel<<<dim3(E/64, MQ/128), 256>>>(QLN, ca_in_w, ca_in_b, nullptr, nullptr, CQH, MQ, E, E, 1.f, EPI_NONE);
    ckv_gemm_kernel<<<dim3(E/64, MTOK/128, 2), 256>>>(OX, ca_in_w, ca_in_b, CKH, CVH);
    attn_bf16_kernel<<<dim3(NQ/64, HEADS, Bb), 128>>>(
        CQH, CKH, CVH, nullptr, nullptr, CAO, NQ, L, SCALING);
    gemm_kernel<<<dim3(E/64, MQ/128), 256>>>(CAO, ca_out_w, ca_out_b, queries, Q2, nullptr, MQ, E, E, 1.f, EPI_NONE);
    // 8. FFN on queries
    ln_kernel<<<MQ, 256>>>(Q2, ln2_g, ln2_b, QLN2);
    gemm_kernel<<<dim3(FFN/64, MQ/128), 256>>>(QLN2, fc1_w, fc1_b, nullptr, QFF, nullptr, MQ, FFN, E, 1.f, EPI_GELU);
    gemm_kernel<<<dim3(E/64, MQ/128), 256>>>(QFF, fc2_w, fc2_b, Q2, OQ, nullptr, MQ, E, FFN, 1.f, EPI_NONE);
}

// round 6
// speedup vs baseline: 4.7836x; 1.1146x over previous
#include <cuda_runtime.h>
#include <cuda_fp16.h>
#include <math.h>
#include <stdint.h>

#define Bb 8
#define HH 32
#define WW 32
#define E 256
#define HEADS 8
#define KD 32
#define FFN 1024
#define NQ 64
#define L 1024
#define SCALING 0.17677669529663687f
#define LOG2E 1.4426950408889634f

#define EPI_NONE 0
#define EPI_GELU 1
#define EPI_THETA 2

// ---------------- scratch arena (float units) ----------------
#define SZ_TOK ((size_t)Bb * L * E)        // 2,097,152
#define SZ_QTK ((size_t)Bb * NQ * E)       // 131,072
#define OFF_X1    ((size_t)0)
#define OFF_V     (OFF_X1 + SZ_TOK)
#define OFF_LEPE  (OFF_V + SZ_TOK)
#define OFF_X2    (OFF_LEPE + SZ_TOK)
#define OFF_Q2    (OFF_X2 + SZ_TOK)
// fp16 buffers (size counted in floats = halves/2)
#define OFF_HN    (OFF_Q2 + SZ_QTK)
#define OFF_QH    (OFF_HN + SZ_TOK / 2)
#define OFF_KH    (OFF_QH + SZ_TOK / 2)
#define OFF_VH    (OFF_KH + SZ_TOK / 2)
#define OFF_AOH   (OFF_VH + SZ_TOK / 2)
#define OFF_XH    (OFF_AOH + SZ_TOK / 2)
#define OFF_CKH   (OFF_XH + SZ_TOK / 2)
#define OFF_CVH   (OFF_CKH + SZ_TOK / 2)
#define OFF_FF    (OFF_CVH + SZ_TOK / 2)
#define OFF_CQH   (OFF_FF + (size_t)Bb * L * FFN / 2)
#define OFF_CAOH  (OFF_CQH + SZ_QTK / 2)
#define OFF_QLN   (OFF_CAOH + SZ_QTK / 2)
#define OFF_QLN2  (OFF_QLN + SZ_QTK / 2)
#define OFF_QFF   (OFF_QLN2 + SZ_QTK / 2)
#define OFF_WH    (OFF_QFF + (size_t)Bb * NQ * FFN / 2)
#define SCRATCH_TOTAL (OFF_WH + 524288)

__device__ float g_scratch[SCRATCH_TOTAL];

// fp16 weight arena offsets (half units)
#define WH_WQ    0
#define WH_WK    65536
#define WH_WV    131072
#define WH_WO    196608
#define WH_FC1   262144
#define WH_FC2   524288
#define WH_CAIN  786432
#define WH_CAOUT 983040

// ---------------- helpers ----------------
__device__ __forceinline__ void cp16(void* dst, const void* src) {
    uint32_t d = (uint32_t)__cvta_generic_to_shared(dst);
    asm volatile("cp.async.cg.shared.global [%0], [%1], 16;" :: "r"(d), "l"(src));
}
#define CP_COMMIT() asm volatile("cp.async.commit_group;" ::: "memory")
#define CP_WAIT(N)  asm volatile("cp.async.wait_group %0;" :: "n"(N) : "memory")

__device__ __forceinline__ uint32_t saddr(const void* p) {
    return (uint32_t)__cvta_generic_to_shared(p);
}

#define LDSM_X4(r0, r1, r2, r3, a)                                          \
    asm volatile("ldmatrix.sync.aligned.m8n8.x4.shared.b16 {%0,%1,%2,%3}, [%4];" \
        : "=r"(r0), "=r"(r1), "=r"(r2), "=r"(r3) : "r"(a))
#define LDSM_X4T(r0, r1, r2, r3, a)                                         \
    asm volatile("ldmatrix.sync.aligned.m8n8.x4.trans.shared.b16 {%0,%1,%2,%3}, [%4];" \
        : "=r"(r0), "=r"(r1), "=r"(r2), "=r"(r3) : "r"(a))

#define MMA_F16(acc, a0, a1, a2, a3, b0, b1)                                \
    asm volatile(                                                           \
        "mma.sync.aligned.m16n8k16.row.col.f32.f16.f16.f32 "                \
        "{%0,%1,%2,%3}, {%4,%5,%6,%7}, {%8,%9}, {%0,%1,%2,%3};"             \
        : "+f"(acc[0]), "+f"(acc[1]), "+f"(acc[2]), "+f"(acc[3])            \
        : "r"(a0), "r"(a1), "r"(a2), "r"(a3), "r"(b0), "r"(b1))

// ---------------- weight fp32 -> fp16 conversion ----------------
__global__ void wconv_kernel(const float* __restrict__ wq, const float* __restrict__ wk,
                             const float* __restrict__ wv, const float* __restrict__ wo,
                             const float* __restrict__ fc1, const float* __restrict__ fc2,
                             const float* __restrict__ cain, const float* __restrict__ caout,
                             __half* __restrict__ Wh) {
    const int sizes[8] = {65536, 65536, 65536, 65536, 262144, 262144, 196608, 65536};
    const int offs[8]  = {WH_WQ, WH_WK, WH_WV, WH_WO, WH_FC1, WH_FC2, WH_CAIN, WH_CAOUT};
    int z = blockIdx.y;
    const float* src = z == 0 ? wq : z == 1 ? wk : z == 2 ? wv : z == 3 ? wo
                     : z == 4 ? fc1 : z == 5 ? fc2 : z == 6 ? cain : caout;
    int n = sizes[z];
    __half* dst = Wh + offs[z];
    for (int i = blockIdx.x * 256 + threadIdx.x; i < n; i += gridDim.x * 256)
        dst[i] = __float2half(src[i]);
}

// ---------------- fp16 GEMM core: C = epi(A @ W^T) ----------------------
// Block tile 128x64, k-tile 32, double-buffered cp.async, 8 warps of 32x32.
// Smem rows padded to 40 halves (80B) -> conflict-free ldmatrix (no swizzle).
#define GS 40
__device__ __forceinline__ void gemm16_core(
        const __half* __restrict__ A, const __half* __restrict__ W,
        const float* __restrict__ bias, const float* __restrict__ res,
        float* __restrict__ C, __half* __restrict__ Ch,
        int M, int N, int K, float alpha, int epi,
        const float* __restrict__ sn, const float* __restrict__ cs,
        __half* As, __half* Bs) {
    int tid = threadIdx.x;
    int w = tid >> 5, lane = tid & 31;
    int wm = (w & 3) * 32, wn = (w >> 2) * 32;
    int m0 = blockIdx.y * 128, n0 = blockIdx.x * 64;
    int lg = lane >> 2, lt = lane & 3;
    int ldrow = lane & 15;
    int ldcol = (lane >> 4) * 8;

    float acc[2][4][4] = {};

    auto loadTile = [&](int buf, int k0) {
        __half* Ab = As + buf * 128 * GS;
        __half* Bd = Bs + buf * 64 * GS;
#pragma unroll
        for (int i = 0; i < 2; i++) {
            int id = tid + 256 * i;
            int row = id >> 2, f = id & 3;
            cp16(&Ab[row * GS + f * 8], &A[(size_t)(m0 + row) * K + k0 + f * 8]);
        }
        {
            int row = tid >> 2, f = tid & 3;
            cp16(&Bd[row * GS + f * 8], &W[(size_t)(n0 + row) * K + k0 + f * 8]);
        }
    };

    int KT = K >> 5;
    int buf = 0;
    loadTile(0, 0);
    CP_COMMIT();
    for (int kt = 0; kt < KT; kt++) {
        if (kt + 1 < KT) {
            loadTile(buf ^ 1, (kt + 1) << 5);
            CP_COMMIT();
            CP_WAIT(1);
        } else {
            CP_WAIT(0);
        }
        __syncthreads();
        const __half* Ab = As + buf * 128 * GS;
        const __half* Bd = Bs + buf * 64 * GS;
#pragma unroll
        for (int ks = 0; ks < 2; ks++) {
            uint32_t af[2][4];
#pragma unroll
            for (int mi = 0; mi < 2; mi++)
                LDSM_X4(af[mi][0], af[mi][1], af[mi][2], af[mi][3],
                        saddr(&Ab[(wm + mi * 16 + ldrow) * GS + ks * 16 + ldcol]));
#pragma unroll
            for (int nb = 0; nb < 2; nb++) {
                uint32_t b0, b1, b2, b3;
                LDSM_X4(b0, b1, b2, b3,
                        saddr(&Bd[(wn + nb * 16 + ldrow) * GS + ks * 16 + ldcol]));
#pragma unroll
                for (int mi = 0; mi < 2; mi++) {
                    MMA_F16(acc[mi][nb * 2],     af[mi][0], af[mi][1], af[mi][2], af[mi][3], b0, b2);
                    MMA_F16(acc[mi][nb * 2 + 1], af[mi][0], af[mi][1], af[mi][2], af[mi][3], b1, b3);
                }
            }
        }
        __syncthreads();
        buf ^= 1;
    }

    // epilogue
#pragma unroll
    for (int mi = 0; mi < 2; mi++) {
#pragma unroll
        for (int ni = 0; ni < 4; ni++) {
            int r = m0 + wm + mi * 16 + lg;
            int c = n0 + wn + ni * 8 + lt * 2;
            float b0 = bias[c], b1 = bias[c + 1];
#pragma unroll
            for (int half_ = 0; half_ < 2; half_++) {
                int rr = r + half_ * 8;
                float v0 = (acc[mi][ni][half_ * 2 + 0] + b0) * alpha;
                float v1 = (acc[mi][ni][half_ * 2 + 1] + b1) * alpha;
                if (epi == EPI_GELU) {
                    v0 = 0.5f * v0 * (1.0f + erff(v0 * 0.70710678118654752f));
                    v1 = 0.5f * v1 * (1.0f + erff(v1 * 0.70710678118654752f));
                } else if (epi == EPI_THETA) {
                    int l = rr & (L - 1);
                    int d0 = c & 31;
                    const float* sp = sn + l * KD + d0;
                    const float* cq = cs + l * KD + d0;
                    float s0 = sp[0], s1 = sp[1];
                    float c0 = cq[0], c1 = cq[1];
                    float o0 = v0 * c0 - v1 * s0;
                    float o1 = v1 * c1 + v0 * s1;
                    v0 = o0; v1 = o1;
                }
                if (res) {
                    v0 += res[(size_t)rr * N + c];
                    v1 += res[(size_t)rr * N + c + 1];
                }
                if (C)
                    *(float2*)&C[(size_t)rr * N + c] = make_float2(v0, v1);
                if (Ch)
                    *(__half2*)&Ch[(size_t)rr * N + c] = __floats2half2_rn(v0, v1);
            }
        }
    }
}

__global__ __launch_bounds__(256) void gemm_kernel(
        const __half* __restrict__ A, const __half* __restrict__ W,
        const float* __restrict__ bias, const float* __restrict__ res,
        float* __restrict__ C, __half* __restrict__ Ch,
        int M, int N, int K, float alpha, int epi) {
    __shared__ __align__(16) __half As[2 * 128 * GS];
    __shared__ __align__(16) __half Bs[2 * 64 * GS];
    gemm16_core(A, W, bias, res, C, Ch, M, N, K, alpha, epi, nullptr, nullptr, As, Bs);
}

__global__ __launch_bounds__(256) void qkv_gemm_kernel(
        const __half* __restrict__ HN, const __half* __restrict__ Wh,
        const float* __restrict__ bq, const float* __restrict__ bk,
        const float* __restrict__ bv,
        __half* __restrict__ QH, __half* __restrict__ KH,
        float* __restrict__ Vb, __half* __restrict__ VH,
        const float* __restrict__ sn, const float* __restrict__ cs) {
    __shared__ __align__(16) __half As[2 * 128 * GS];
    __shared__ __align__(16) __half Bs[2 * 64 * GS];
    int z = blockIdx.z;
    const __half* W = Wh + (z == 0 ? WH_WQ : z == 1 ? WH_WK : WH_WV);
    const float* bias = (z == 0) ? bq : (z == 1) ? bk : bv;
    float* C = (z == 2) ? Vb : nullptr;
    __half* Ch = (z == 0) ? QH : (z == 1) ? KH : VH;
    float alpha = (z == 1) ? SCALING : 1.f;
    int epi = (z == 2) ? EPI_NONE : EPI_THETA;
    gemm16_core(HN, W, bias, nullptr, C, Ch, Bb * L, E, E, alpha, epi, sn, cs, As, Bs);
}

__global__ __launch_bounds__(256) void ckv_gemm_kernel(
        const __half* __restrict__ XH, const __half* __restrict__ Wh,
        const float* __restrict__ ca_in_b,
        __half* __restrict__ CKH, __half* __restrict__ CVH) {
    __shared__ __align__(16) __half As[2 * 128 * GS];
    __shared__ __align__(16) __half Bs[2 * 64 * GS];
    int z = blockIdx.z;
    const __half* W = Wh + WH_CAIN + (size_t)(z + 1) * E * E;
    const float* bias = ca_in_b + (z + 1) * E;
    __half* Ch = z ? CVH : CKH;
    gemm16_core(XH, W, bias, nullptr, nullptr, Ch, Bb * L, E, E, 1.f, EPI_NONE,
                nullptr, nullptr, As, Bs);
}

// ---------------- fused dwconv3x3(+in) + LN1 --------------------------
__global__ void dwconv3_ln_kernel(const float* __restrict__ in,
                                  const float* __restrict__ w,
                                  const float* __restrict__ bias,
                                  const float* __restrict__ g,
                                  const float* __restrict__ bln,
                                  float* __restrict__ X1,
                                  __half* __restrict__ HN) {
    int c = threadIdx.x;
    int wx = blockIdx.x, hy = blockIdx.y, b = blockIdx.z;
    float acc = bias[c];
#pragma unroll
    for (int kh = 0; kh < 3; kh++) {
        int y = hy + kh - 1;
        if (y < 0 || y >= HH) continue;
#pragma unroll
        for (int kw = 0; kw < 3; kw++) {
            int xx = wx + kw - 1;
            if (xx < 0 || xx >= WW) continue;
            acc += in[(((size_t)b * HH + y) * WW + xx) * E + c] *
                   w[c * 9 + kh * 3 + kw];
        }
    }
    size_t o = (((size_t)b * HH + hy) * WW + wx) * E + c;
    float v = in[o] + acc;
    X1[o] = v;
    __shared__ float s1[256], s2[256];
    s1[c] = v; s2[c] = v * v;
    __syncthreads();
    for (int off = 128; off > 0; off >>= 1) {
        if (c < off) { s1[c] += s1[c + off]; s2[c] += s2[c + off]; }
        __syncthreads();
    }
    float m = s1[0] * (1.0f / E);
    float var = s2[0] * (1.0f / E) - m * m;
    float inv = rsqrtf(var + 1e-6f);
    HN[o] = __float2half((v - m) * inv * g[c] + bln[c]);
}

// ---------------- dwconv 5x5 -------------------------------------------
__global__ void dwconv5_kernel(const float* __restrict__ in,
                               const float* __restrict__ w,
                               const float* __restrict__ bias,
                               float* __restrict__ out) {
    int c = threadIdx.x;
    int wx = blockIdx.x, hy = blockIdx.y, b = blockIdx.z;
    float acc = bias[c];
#pragma unroll
    for (int kh = 0; kh < 5; kh++) {
        int y = hy + kh - 2;
        if (y < 0 || y >= HH) continue;
#pragma unroll
        for (int kw = 0; kw < 5; kw++) {
            int xx = wx + kw - 2;
            if (xx < 0 || xx >= WW) continue;
            acc += in[(((size_t)b * HH + y) * WW + xx) * E + c] *
                   w[c * 25 + kh * 5 + kw];
        }
    }
    out[(((size_t)b * HH + hy) * WW + wx) * E + c] = acc;
}

// ---------------- layernorm (fp32 in, fp16 out) ------------------------
__global__ void ln_kernel(const float* __restrict__ in,
                          const float* __restrict__ g,
                          const float* __restrict__ b,
                          __half* __restrict__ out) {
    int row = blockIdx.x;
    int t = threadIdx.x;
    float v = in[(size_t)row * E + t];
    __shared__ float s1[256], s2[256];
    s1[t] = v; s2[t] = v * v;
    __syncthreads();
    for (int o = 128; o > 0; o >>= 1) {
        if (t < o) { s1[t] += s1[t + o]; s2[t] += s2[t + o]; }
        __syncthreads();
    }
    float m = s1[0] * (1.0f / E);
    float var = s2[0] * (1.0f / E) - m * m;
    float inv = rsqrtf(var + 1e-6f);
    out[(size_t)row * E + t] = __float2half((v - m) * inv * g[t] + b[t]);
}

// ---------------- fp16 tensor-core flash attention -----------------------
#define KVS 40
#define PSS 72
__global__ __launch_bounds__(128) void attn_f16_kernel(
        const __half* __restrict__ Q, const __half* __restrict__ Kt,
        const __half* __restrict__ V,
        const float* __restrict__ mask, const float* __restrict__ addend,
        __half* __restrict__ O, int Lq, int Lk, float scale) {
    __shared__ __align__(16) __half Qs[64 * KVS];
    __shared__ __align__(16) __half Ks[2][64 * KVS];
    __shared__ __align__(16) __half Vs[2][64 * KVS];
    __shared__ __align__(16) __half Ps[64 * PSS];

    int tid = threadIdx.x;
    int w = tid >> 5, lane = tid & 31;
    int lg = lane >> 2, lt = lane & 3;
    int h = blockIdx.y, b = blockIdx.z;
    int q0 = blockIdx.x * 64;
    int wm = w * 16;
    int ldrow = lane & 15;
    int ldcol = (lane >> 4) * 8;

    auto loadTile = [&](__half* dst, const __half* src) {
#pragma unroll
        for (int i = 0; i < 2; i++) {
            int id = tid + 128 * i;
            int row = id >> 2, gr = id & 3;
            cp16(dst + row * KVS + gr * 8, src + (size_t)row * E + gr * 8);
        }
    };

    loadTile(Qs, Q + ((size_t)(b * Lq + q0)) * E + h * KD);
    CP_COMMIT();
    loadTile(Ks[0], Kt + ((size_t)(b * Lk)) * E + h * KD);
    loadTile(Vs[0], V + ((size_t)(b * Lk)) * E + h * KD);
    CP_COMMIT();
    CP_WAIT(1);
    __syncthreads();

    uint32_t qf[2][4];
#pragma unroll
    for (int ks = 0; ks < 2; ks++)
        LDSM_X4(qf[ks][0], qf[ks][1], qf[ks][2], qf[ks][3],
                saddr(&Qs[(wm + ldrow) * KVS + ks * 16 + ldcol]));

    float m0 = -INFINITY, m1 = -INFINITY, l0 = 0.f, l1 = 0.f;
    float oacc[4][4] = {};
    const float* mbase = mask ? (mask + ((size_t)h * Lk + q0) * Lk) : nullptr;

    int buf = 0;
    int NJ = Lk >> 6;
    for (int jt = 0; jt < NJ; jt++) {
        int j0 = jt << 6;
        if (jt + 1 < NJ) {
            loadTile(Ks[buf ^ 1], Kt + ((size_t)(b * Lk + j0 + 64)) * E + h * KD);
            loadTile(Vs[buf ^ 1], V  + ((size_t)(b * Lk + j0 + 64)) * E + h * KD);
            CP_COMMIT();
            CP_WAIT(1);
        } else {
            CP_WAIT(0);
        }
        __syncthreads();

        float2 mv[8][2];
        if (mbase) {
            int r0 = wm + lg, r1 = wm + 8 + lg;
#pragma unroll
            for (int ni = 0; ni < 8; ni++) {
                int c = j0 + ni * 8 + lt * 2;
                mv[ni][0] = *(const float2*)&mbase[(size_t)r0 * Lk + c];
                mv[ni][1] = *(const float2*)&mbase[(size_t)r1 * Lk + c];
            }
        }

        float sacc[8][4];
#pragma unroll
        for (int ni = 0; ni < 8; ni++)
#pragma unroll
            for (int c = 0; c < 4; c++) sacc[ni][c] = 0.f;
#pragma unroll
        for (int ks = 0; ks < 2; ks++) {
#pragma unroll
            for (int nb = 0; nb < 4; nb++) {
                uint32_t r0, r1, r2, r3;
                LDSM_X4(r0, r1, r2, r3,
                        saddr(&Ks[buf][(nb * 16 + ldrow) * KVS + ks * 16 + ldcol]));
                MMA_F16(sacc[2 * nb],     qf[ks][0], qf[ks][1], qf[ks][2], qf[ks][3], r0, r2);
                MMA_F16(sacc[2 * nb + 1], qf[ks][0], qf[ks][1], qf[ks][2], qf[ks][3], r1, r3);
            }
        }

        if (mbase) {
#pragma unroll
            for (int ni = 0; ni < 8; ni++) {
                sacc[ni][0] = sacc[ni][0] * scale + mv[ni][0].x;
                sacc[ni][1] = sacc[ni][1] * scale + mv[ni][0].y;
                sacc[ni][2] = sacc[ni][2] * scale + mv[ni][1].x;
                sacc[ni][3] = sacc[ni][3] * scale + mv[ni][1].y;
            }
        } else if (scale != 1.f) {
#pragma unroll
            for (int ni = 0; ni < 8; ni++)
#pragma unroll
                for (int c = 0; c < 4; c++) sacc[ni][c] *= scale;
        }

        float rm0 = -INFINITY, rm1 = -INFINITY;
#pragma unroll
        for (int ni = 0; ni < 8; ni++) {
            rm0 = fmaxf(rm0, fmaxf(sacc[ni][0], sacc[ni][1]));
            rm1 = fmaxf(rm1, fmaxf(sacc[ni][2], sacc[ni][3]));
        }
        rm0 = fmaxf(rm0, __shfl_xor_sync(0xffffffff, rm0, 1));
        rm0 = fmaxf(rm0, __shfl_xor_sync(0xffffffff, rm0, 2));
        rm1 = fmaxf(rm1, __shfl_xor_sync(0xffffffff, rm1, 1));
        rm1 = fmaxf(rm1, __shfl_xor_sync(0xffffffff, rm1, 2));
        float mn0 = fmaxf(m0, rm0), mn1 = fmaxf(m1, rm1);
        float al0 = exp2f((m0 - mn0) * LOG2E);
        float al1 = exp2f((m1 - mn1) * LOG2E);
        float rs0 = 0.f, rs1 = 0.f;
#pragma unroll
        for (int ni = 0; ni < 8; ni++) {
            float p0 = exp2f((sacc[ni][0] - mn0) * LOG2E);
            float p1 = exp2f((sacc[ni][1] - mn0) * LOG2E);
            float p2 = exp2f((sacc[ni][2] - mn1) * LOG2E);
            float p3 = exp2f((sacc[ni][3] - mn1) * LOG2E);
            rs0 += p0 + p1; rs1 += p2 + p3;
            int c = ni * 8 + lt * 2;
            *(__half2*)&Ps[(wm + lg) * PSS + c]     = __floats2half2_rn(p0, p1);
            *(__half2*)&Ps[(wm + 8 + lg) * PSS + c] = __floats2half2_rn(p2, p3);
        }
        rs0 += __shfl_xor_sync(0xffffffff, rs0, 1);
        rs0 += __shfl_xor_sync(0xffffffff, rs0, 2);
        rs1 += __shfl_xor_sync(0xffffffff, rs1, 1);
        rs1 += __shfl_xor_sync(0xffffffff, rs1, 2);
        l0 = l0 * al0 + rs0;
        l1 = l1 * al1 + rs1;
        m0 = mn0; m1 = mn1;
#pragma unroll
        for (int ni = 0; ni < 4; ni++) {
            oacc[ni][0] *= al0; oacc[ni][1] *= al0;
            oacc[ni][2] *= al1; oacc[ni][3] *= al1;
        }
        __syncwarp();

#pragma unroll
        for (int ks = 0; ks < 4; ks++) {
            uint32_t pa0, pa1, pa2, pa3;
            LDSM_X4(pa0, pa1, pa2, pa3,
                    saddr(&Ps[(wm + ldrow) * PSS + ks * 16 + ldcol]));
            uint32_t v0, v1, v2, v3;
            LDSM_X4T(v0, v1, v2, v3,
                     saddr(&Vs[buf][(ks * 16 + ldrow) * KVS + 0 + ldcol]));
            uint32_t u0, u1, u2, u3;
            LDSM_X4T(u0, u1, u2, u3,
                     saddr(&Vs[buf][(ks * 16 + ldrow) * KVS + 16 + ldcol]));
            MMA_F16(oacc[0], pa0, pa1, pa2, pa3, v0, v1);
            MMA_F16(oacc[1], pa0, pa1, pa2, pa3, v2, v3);
            MMA_F16(oacc[2], pa0, pa1, pa2, pa3, u0, u1);
            MMA_F16(oacc[3], pa0, pa1, pa2, pa3, u2, u3);
        }
        __syncthreads();
        buf ^= 1;
    }

    float inv0 = 1.f / l0, inv1 = 1.f / l1;
    int r0 = q0 + wm + lg, r1 = r0 + 8;
#pragma unroll
    for (int ni = 0; ni < 4; ni++) {
        int c = h * KD + ni * 8 + lt * 2;
        float v00 = oacc[ni][0] * inv0, v01 = oacc[ni][1] * inv0;
        float v10 = oacc[ni][2] * inv1, v11 = oacc[ni][3] * inv1;
        if (addend) {
            float2 a0 = *(const float2*)&addend[((size_t)(b * Lq + r0)) * E + c];
            float2 a1 = *(const float2*)&addend[((size_t)(b * Lq + r1)) * E + c];
            v00 += a0.x; v01 += a0.y; v10 += a1.x; v11 += a1.y;
        }
        *(__half2*)&O[((size_t)(b * Lq + r0)) * E + c] = __floats2half2_rn(v00, v01);
        *(__half2*)&O[((size_t)(b * Lq + r1)) * E + c] = __floats2half2_rn(v10, v11);
    }
}

// ---------------- launcher ----------------------------------------------
extern "C" void kernel_launch(void* const* d_in, const int* in_sizes, int n_in,
                              void* d_out, int out_size) {
    const float* x       = (const float*)d_in[0];
    const float* queries = (const float*)d_in[1];
    const float* sn      = (const float*)d_in[2];
    const float* cs      = (const float*)d_in[3];
    const float* mask    = (const float*)d_in[4];
    const float* ln1_g   = (const float*)d_in[5];
    const float* ln1_b   = (const float*)d_in[6];
    const float* ln2_g   = (const float*)d_in[7];
    const float* ln2_b   = (const float*)d_in[8];
    const float* wq      = (const float*)d_in[9];
    const float* bq      = (const float*)d_in[10];
    const float* wk      = (const float*)d_in[11];
    const float* bk      = (const float*)d_in[12];
    const float* wv      = (const float*)d_in[13];
    const float* bv      = (const float*)d_in[14];
    const float* lepe_w  = (const float*)d_in[15];
    const float* lepe_b  = (const float*)d_in[16];
    const float* wo      = (const float*)d_in[17];
    const float* bo      = (const float*)d_in[18];
    const float* fc1_w   = (const float*)d_in[19];
    const float* fc1_b   = (const float*)d_in[20];
    const float* fc2_w   = (const float*)d_in[21];
    const float* fc2_b   = (const float*)d_in[22];
    const float* pos_w   = (const float*)d_in[23];
    const float* pos_b   = (const float*)d_in[24];
    const float* ca_in_w = (const float*)d_in[25];
    const float* ca_in_b = (const float*)d_in[26];
    const float* ca_out_w= (const float*)d_in[27];
    const float* ca_out_b= (const float*)d_in[28];

    void* sp = nullptr;
    cudaGetSymbolAddress(&sp, g_scratch);
    float* S = (float*)sp;
    float* X1   = S + OFF_X1;
    float* Vb   = S + OFF_V;
    float* LEPE = S + OFF_LEPE;
    float* X2   = S + OFF_X2;
    float* Q2   = S + OFF_Q2;
    __half* HN   = (__half*)(S + OFF_HN);
    __half* QH   = (__half*)(S + OFF_QH);
    __half* KH   = (__half*)(S + OFF_KH);
    __half* VH   = (__half*)(S + OFF_VH);
    __half* AOH  = (__half*)(S + OFF_AOH);
    __half* XH   = (__half*)(S + OFF_XH);
    __half* CKH  = (__half*)(S + OFF_CKH);
    __half* CVH  = (__half*)(S + OFF_CVH);
    __half* FF   = (__half*)(S + OFF_FF);
    __half* CQH  = (__half*)(S + OFF_CQH);
    __half* CAOH = (__half*)(S + OFF_CAOH);
    __half* QLN  = (__half*)(S + OFF_QLN);
    __half* QLN2 = (__half*)(S + OFF_QLN2);
    __half* QFF  = (__half*)(S + OFF_QFF);
    __half* WHb  = (__half*)(S + OFF_WH);

    float* OX = (float*)d_out;
    float* OQ = OX + (size_t)Bb * L * E;

    const int MTOK = Bb * L;   // 8192
    const int MQ   = Bb * NQ;  // 512
    dim3 sp3(WW, HH, Bb);

    // 0. weights -> fp16
    wconv_kernel<<<dim3(128, 8), 256>>>(wq, wk, wv, wo, fc1_w, fc2_w,
                                        ca_in_w, ca_out_w, WHb);
    // 1. x1 = x + dwconv3(x); hn = LN1(x1) fp16
    dwconv3_ln_kernel<<<sp3, 256>>>(x, pos_w, pos_b, ln1_g, ln1_b, X1, HN);
    // 2. q(theta), k(theta,*scaling), v(fp32+fp16)
    qkv_gemm_kernel<<<dim3(E/64, MTOK/128, 3), 256>>>(
        HN, WHb, bq, bk, bv, QH, KH, Vb, VH, sn, cs);
    // 3. lepe = dwconv5(v)
    dwconv5_kernel<<<sp3, 256>>>(Vb, lepe_w, lepe_b, LEPE);
    // 4. self attention + lepe -> AOH fp16
    attn_f16_kernel<<<dim3(L/64, HEADS, Bb), 128>>>(
        QH, KH, VH, mask, LEPE, AOH, L, L, 1.f);
    // 5. x2 = x1 + aoh @ wo^T + bo
    gemm_kernel<<<dim3(E/64, MTOK/128), 256>>>(AOH, WHb + WH_WO, bo, X1, X2, nullptr, MTOK, E, E, 1.f, EPI_NONE);
    // 6. FFN on x
    ln_kernel<<<MTOK, 256>>>(X2, ln2_g, ln2_b, HN);
    gemm_kernel<<<dim3(FFN/64, MTOK/128), 256>>>(HN, WHb + WH_FC1, fc1_b, nullptr, nullptr, FF, MTOK, FFN, E, 1.f, EPI_GELU);
    gemm_kernel<<<dim3(E/64, MTOK/128), 256>>>(FF, WHb + WH_FC2, fc2_b, X2, OX, XH, MTOK, E, FFN, 1.f, EPI_NONE);
    // 7. cross attention
    ln_kernel<<<MQ, 256>>>(queries, ln1_g, ln1_b, QLN);
    gemm_kernel<<<dim3(E/64, MQ/128), 256>>>(QLN, WHb + WH_CAIN, ca_in_b, nullptr, nullptr, CQH, MQ, E, E, 1.f, EPI_NONE);
    ckv_gemm_kernel<<<dim3(E/64, MTOK/128, 2), 256>>>(XH, WHb, ca_in_b, CKH, CVH);
    attn_f16_kernel<<<dim3(NQ/64, HEADS, Bb), 128>>>(
        CQH, CKH, CVH, nullptr, nullptr, CAOH, NQ, L, SCALING);
    gemm_kernel<<<dim3(E/64, MQ/128), 256>>>(CAOH, WHb + WH_CAOUT, ca_out_b, queries, Q2, nullptr, MQ, E, E, 1.f, EPI_NONE);
    // 8. FFN on queries
    ln_kernel<<<MQ, 256>>>(Q2, ln2_g, ln2_b, QLN2);
    gemm_kernel<<<dim3(FFN/64, MQ/128), 256>>>(QLN2, WHb + WH_FC1, fc1_b, nullptr, nullptr, QFF, MQ, FFN, E, 1.f, EPI_GELU);
    gemm_kernel<<<dim3(E/64, MQ/128), 256>>>(QFF, WHb + WH_FC2, fc2_b, Q2, OQ, nullptr, MQ, E, FFN, 1.f, EPI_NONE);
}

// round 7
// speedup vs baseline: 5.5943x; 1.1695x over previous
#include <cuda_runtime.h>
#include <cuda_fp16.h>
#include <math.h>
#include <stdint.h>

#define Bb 8
#define HH 32
#define WW 32
#define E 256
#define HEADS 8
#define KD 32
#define FFN 1024
#define NQ 64
#define L 1024
#define SCALING 0.17677669529663687f
#define LOG2E 1.4426950408889634f

#define EPI_NONE 0
#define EPI_GELU 1
#define EPI_THETA 2

// ---------------- scratch arena (float units) ----------------
#define SZ_TOK ((size_t)Bb * L * E)
#define SZ_QTK ((size_t)Bb * NQ * E)
#define OFF_X1    ((size_t)0)
#define OFF_LEPE  (OFF_X1 + SZ_TOK)
#define OFF_X2    (OFF_LEPE + SZ_TOK)
#define OFF_Q2    (OFF_X2 + SZ_TOK)
// fp16 buffers (size counted in floats = halves/2)
#define OFF_HN    (OFF_Q2 + SZ_QTK)
#define OFF_QH    (OFF_HN + SZ_TOK / 2)
#define OFF_KH    (OFF_QH + SZ_TOK / 2)
#define OFF_VH    (OFF_KH + SZ_TOK / 2)
#define OFF_AOH   (OFF_VH + SZ_TOK / 2)
#define OFF_XH    (OFF_AOH + SZ_TOK / 2)
#define OFF_CKH   (OFF_XH + SZ_TOK / 2)
#define OFF_CVH   (OFF_CKH + SZ_TOK / 2)
#define OFF_FF    (OFF_CVH + SZ_TOK / 2)
#define OFF_CQH   (OFF_FF + (size_t)Bb * L * FFN / 2)
#define OFF_CAOH  (OFF_CQH + SZ_QTK / 2)
#define OFF_QLN   (OFF_CAOH + SZ_QTK / 2)
#define OFF_QLN2  (OFF_QLN + SZ_QTK / 2)
#define OFF_QFF   (OFF_QLN2 + SZ_QTK / 2)
#define OFF_WH    (OFF_QFF + (size_t)Bb * NQ * FFN / 2)
#define SCRATCH_TOTAL (OFF_WH + 524288)

__device__ float g_scratch[SCRATCH_TOTAL];

// fp16 weight arena offsets (half units)
#define WH_WQ    0
#define WH_WK    65536
#define WH_WV    131072
#define WH_WO    196608
#define WH_FC1   262144
#define WH_FC2   524288
#define WH_CAIN  786432
#define WH_CAOUT 983040

// ---------------- helpers ----------------
__device__ __forceinline__ void cp16(void* dst, const void* src) {
    uint32_t d = (uint32_t)__cvta_generic_to_shared(dst);
    asm volatile("cp.async.cg.shared.global [%0], [%1], 16;" :: "r"(d), "l"(src));
}
#define CP_COMMIT() asm volatile("cp.async.commit_group;" ::: "memory")
#define CP_WAIT(N)  asm volatile("cp.async.wait_group %0;" :: "n"(N) : "memory")

__device__ __forceinline__ uint32_t saddr(const void* p) {
    return (uint32_t)__cvta_generic_to_shared(p);
}

#define LDSM_X4(r0, r1, r2, r3, a)                                          \
    asm volatile("ldmatrix.sync.aligned.m8n8.x4.shared.b16 {%0,%1,%2,%3}, [%4];" \
        : "=r"(r0), "=r"(r1), "=r"(r2), "=r"(r3) : "r"(a))
#define LDSM_X4T(r0, r1, r2, r3, a)                                         \
    asm volatile("ldmatrix.sync.aligned.m8n8.x4.trans.shared.b16 {%0,%1,%2,%3}, [%4];" \
        : "=r"(r0), "=r"(r1), "=r"(r2), "=r"(r3) : "r"(a))

#define MMA_F16(acc, a0, a1, a2, a3, b0, b1)                                \
    asm volatile(                                                           \
        "mma.sync.aligned.m16n8k16.row.col.f32.f16.f16.f32 "                \
        "{%0,%1,%2,%3}, {%4,%5,%6,%7}, {%8,%9}, {%0,%1,%2,%3};"             \
        : "+f"(acc[0]), "+f"(acc[1]), "+f"(acc[2]), "+f"(acc[3])            \
        : "r"(a0), "r"(a1), "r"(a2), "r"(a3), "r"(b0), "r"(b1))

// warp+block reduction of (sum, sumsq) over 256 threads -> smem[0], smem[1]
__device__ __forceinline__ void blk_reduce2(float v, float q, float* out2,
                                            int tid) {
    __shared__ float ws[8], wq[8];
#pragma unroll
    for (int o = 16; o > 0; o >>= 1) {
        v += __shfl_xor_sync(0xffffffff, v, o);
        q += __shfl_xor_sync(0xffffffff, q, o);
    }
    if ((tid & 31) == 0) { ws[tid >> 5] = v; wq[tid >> 5] = q; }
    __syncthreads();
    if (tid < 32) {
        float a = (tid < 8) ? ws[tid] : 0.f;
        float b = (tid < 8) ? wq[tid] : 0.f;
#pragma unroll
        for (int o = 4; o > 0; o >>= 1) {
            a += __shfl_xor_sync(0xffffffff, a, o);
            b += __shfl_xor_sync(0xffffffff, b, o);
        }
        if (tid == 0) { out2[0] = a; out2[1] = b; }
    }
    __syncthreads();
}

// ---------------- weight fp32 -> fp16 conversion ----------------
__global__ void wconv_kernel(const float* __restrict__ wq, const float* __restrict__ wk,
                             const float* __restrict__ wv, const float* __restrict__ wo,
                             const float* __restrict__ fc1, const float* __restrict__ fc2,
                             const float* __restrict__ cain, const float* __restrict__ caout,
                             __half* __restrict__ Wh) {
    const int sizes[8] = {65536, 65536, 65536, 65536, 262144, 262144, 196608, 65536};
    const int offs[8]  = {WH_WQ, WH_WK, WH_WV, WH_WO, WH_FC1, WH_FC2, WH_CAIN, WH_CAOUT};
    int z = blockIdx.y;
    const float* src = z == 0 ? wq : z == 1 ? wk : z == 2 ? wv : z == 3 ? wo
                     : z == 4 ? fc1 : z == 5 ? fc2 : z == 6 ? cain : caout;
    int n = sizes[z];
    __half* dst = Wh + offs[z];
    for (int i = blockIdx.x * 256 + threadIdx.x; i < n; i += gridDim.x * 256)
        dst[i] = __float2half(src[i]);
}

// ---------------- fp16 GEMM core (3-stage pipeline) ----------------------
#define GS 40
__device__ __forceinline__ void gemm16_core(
        const __half* __restrict__ A, const __half* __restrict__ W,
        const float* __restrict__ bias, const float* __restrict__ res,
        float* __restrict__ C, __half* __restrict__ Ch,
        int M, int N, int K, float alpha, int epi,
        const float* __restrict__ sn, const float* __restrict__ cs,
        __half* As, __half* Bs) {
    int tid = threadIdx.x;
    int w = tid >> 5, lane = tid & 31;
    int wm = (w & 3) * 32, wn = (w >> 2) * 32;
    int m0 = blockIdx.y * 128, n0 = blockIdx.x * 64;
    int lg = lane >> 2, lt = lane & 3;
    int ldrow = lane & 15;
    int ldcol = (lane >> 4) * 8;

    float acc[2][4][4] = {};

    auto loadTile = [&](int s, int k0) {
        __half* Ab = As + s * 128 * GS;
        __half* Bd = Bs + s * 64 * GS;
#pragma unroll
        for (int i = 0; i < 2; i++) {
            int id = tid + 256 * i;
            int row = id >> 2, f = id & 3;
            cp16(&Ab[row * GS + f * 8], &A[(size_t)(m0 + row) * K + k0 + f * 8]);
        }
        {
            int row = tid >> 2, f = tid & 3;
            cp16(&Bd[row * GS + f * 8], &W[(size_t)(n0 + row) * K + k0 + f * 8]);
        }
    };

    int KT = K >> 5;
    loadTile(0, 0);
    CP_COMMIT();
    if (KT > 1) { loadTile(1, 32); CP_COMMIT(); }
    for (int kt = 0; kt < KT; kt++) {
        if (kt + 1 < KT) { CP_WAIT(1); } else { CP_WAIT(0); }
        __syncthreads();
        int s = kt % 3;
        const __half* Ab = As + s * 128 * GS;
        const __half* Bd = Bs + s * 64 * GS;
#pragma unroll
        for (int ks = 0; ks < 2; ks++) {
            uint32_t af[2][4];
#pragma unroll
            for (int mi = 0; mi < 2; mi++)
                LDSM_X4(af[mi][0], af[mi][1], af[mi][2], af[mi][3],
                        saddr(&Ab[(wm + mi * 16 + ldrow) * GS + ks * 16 + ldcol]));
#pragma unroll
            for (int nb = 0; nb < 2; nb++) {
                uint32_t b0, b1, b2, b3;
                LDSM_X4(b0, b1, b2, b3,
                        saddr(&Bd[(wn + nb * 16 + ldrow) * GS + ks * 16 + ldcol]));
#pragma unroll
                for (int mi = 0; mi < 2; mi++) {
                    MMA_F16(acc[mi][nb * 2],     af[mi][0], af[mi][1], af[mi][2], af[mi][3], b0, b2);
                    MMA_F16(acc[mi][nb * 2 + 1], af[mi][0], af[mi][1], af[mi][2], af[mi][3], b1, b3);
                }
            }
        }
        if (kt + 2 < KT) { loadTile((kt + 2) % 3, (kt + 2) << 5); CP_COMMIT(); }
    }

    // epilogue
#pragma unroll
    for (int mi = 0; mi < 2; mi++) {
#pragma unroll
        for (int ni = 0; ni < 4; ni++) {
            int r = m0 + wm + mi * 16 + lg;
            int c = n0 + wn + ni * 8 + lt * 2;
            float b0 = bias[c], b1 = bias[c + 1];
#pragma unroll
            for (int half_ = 0; half_ < 2; half_++) {
                int rr = r + half_ * 8;
                float v0 = (acc[mi][ni][half_ * 2 + 0] + b0) * alpha;
                float v1 = (acc[mi][ni][half_ * 2 + 1] + b1) * alpha;
                if (epi == EPI_GELU) {
                    v0 = 0.5f * v0 * (1.0f + erff(v0 * 0.70710678118654752f));
                    v1 = 0.5f * v1 * (1.0f + erff(v1 * 0.70710678118654752f));
                } else if (epi == EPI_THETA) {
                    int l = rr & (L - 1);
                    int d0 = c & 31;
                    const float* sp = sn + l * KD + d0;
                    const float* cq = cs + l * KD + d0;
                    float s0 = sp[0], s1 = sp[1];
                    float c0 = cq[0], c1 = cq[1];
                    float o0 = v0 * c0 - v1 * s0;
                    float o1 = v1 * c1 + v0 * s1;
                    v0 = o0; v1 = o1;
                }
                if (res) {
                    v0 += res[(size_t)rr * N + c];
                    v1 += res[(size_t)rr * N + c + 1];
                }
                if (C)
                    *(float2*)&C[(size_t)rr * N + c] = make_float2(v0, v1);
                if (Ch)
                    *(__half2*)&Ch[(size_t)rr * N + c] = __floats2half2_rn(v0, v1);
            }
        }
    }
}

__global__ __launch_bounds__(256) void gemm_kernel(
        const __half* __restrict__ A, const __half* __restrict__ W,
        const float* __restrict__ bias, const float* __restrict__ res,
        float* __restrict__ C, __half* __restrict__ Ch,
        int M, int N, int K, float alpha, int epi) {
    __shared__ __align__(16) __half As[3 * 128 * GS];
    __shared__ __align__(16) __half Bs[3 * 64 * GS];
    gemm16_core(A, W, bias, res, C, Ch, M, N, K, alpha, epi, nullptr, nullptr, As, Bs);
}

__global__ __launch_bounds__(256) void qkv_gemm_kernel(
        const __half* __restrict__ HN, const __half* __restrict__ Wh,
        const float* __restrict__ bq, const float* __restrict__ bk,
        const float* __restrict__ bv,
        __half* __restrict__ QH, __half* __restrict__ KH,
        __half* __restrict__ VH,
        const float* __restrict__ sn, const float* __restrict__ cs) {
    __shared__ __align__(16) __half As[3 * 128 * GS];
    __shared__ __align__(16) __half Bs[3 * 64 * GS];
    int z = blockIdx.z;
    const __half* W = Wh + (z == 0 ? WH_WQ : z == 1 ? WH_WK : WH_WV);
    const float* bias = (z == 0) ? bq : (z == 1) ? bk : bv;
    __half* Ch = (z == 0) ? QH : (z == 1) ? KH : VH;
    float alpha = (z == 1) ? SCALING : 1.f;
    int epi = (z == 2) ? EPI_NONE : EPI_THETA;
    gemm16_core(HN, W, bias, nullptr, nullptr, Ch, Bb * L, E, E, alpha, epi, sn, cs, As, Bs);
}

__global__ __launch_bounds__(256) void ckv_gemm_kernel(
        const __half* __restrict__ XH, const __half* __restrict__ Wh,
        const float* __restrict__ ca_in_b,
        __half* __restrict__ CKH, __half* __restrict__ CVH) {
    __shared__ __align__(16) __half As[3 * 128 * GS];
    __shared__ __align__(16) __half Bs[3 * 64 * GS];
    int z = blockIdx.z;
    const __half* W = Wh + WH_CAIN + (size_t)(z + 1) * E * E;
    const float* bias = ca_in_b + (z + 1) * E;
    __half* Ch = z ? CVH : CKH;
    gemm16_core(XH, W, bias, nullptr, nullptr, Ch, Bb * L, E, E, 1.f, EPI_NONE,
                nullptr, nullptr, As, Bs);
}

// ---------------- fused dwconv3x3(+in) + LN1 --------------------------
__global__ void dwconv3_ln_kernel(const float* __restrict__ in,
                                  const float* __restrict__ w,
                                  const float* __restrict__ bias,
                                  const float* __restrict__ g,
                                  const float* __restrict__ bln,
                                  float* __restrict__ X1,
                                  __half* __restrict__ HN) {
    int c = threadIdx.x;
    int wx = blockIdx.x, hy = blockIdx.y, b = blockIdx.z;
    float acc = bias[c];
#pragma unroll
    for (int kh = 0; kh < 3; kh++) {
        int y = hy + kh - 1;
        if (y < 0 || y >= HH) continue;
#pragma unroll
        for (int kw = 0; kw < 3; kw++) {
            int xx = wx + kw - 1;
            if (xx < 0 || xx >= WW) continue;
            acc += in[(((size_t)b * HH + y) * WW + xx) * E + c] *
                   w[c * 9 + kh * 3 + kw];
        }
    }
    size_t o = (((size_t)b * HH + hy) * WW + wx) * E + c;
    float v = in[o] + acc;
    X1[o] = v;
    __shared__ float red[2];
    blk_reduce2(v, v * v, red, c);
    float m = red[0] * (1.0f / E);
    float var = red[1] * (1.0f / E) - m * m;
    float inv = rsqrtf(var + 1e-6f);
    HN[o] = __float2half((v - m) * inv * g[c] + bln[c]);
}

// ---------------- dwconv 5x5: fp16 in, fp32 out, 4 px/thread -----------
__global__ __launch_bounds__(256) void dwconv5_kernel(
        const __half* __restrict__ VH, const float* __restrict__ w,
        const float* __restrict__ bias, float* __restrict__ out) {
    int c = threadIdx.x;
    int x0 = blockIdx.x * 4, hy = blockIdx.y, b = blockIdx.z;
    float wreg[25];
#pragma unroll
    for (int i = 0; i < 25; i++) wreg[i] = w[c * 25 + i];
    float bz = bias[c];
    float acc[4] = {bz, bz, bz, bz};
#pragma unroll
    for (int kh = 0; kh < 5; kh++) {
        int y = hy + kh - 2;
        if (y < 0 || y >= HH) continue;
        const __half* rbase = VH + (((size_t)b * HH + y) * WW) * E + c;
#pragma unroll
        for (int kw = 0; kw < 8; kw++) {
            int xx = x0 + kw - 2;
            if (xx < 0 || xx >= WW) continue;
            float v = __half2float(rbase[(size_t)xx * E]);
            int dx = kw - 2;  // xx - x0
#pragma unroll
            for (int j = 0; j < 4; j++) {
                int kwi = dx - j + 2;
                if (kwi >= 0 && kwi < 5)
                    acc[j] += v * wreg[kh * 5 + kwi];
            }
        }
    }
    size_t obase = (((size_t)b * HH + hy) * WW + x0) * E + c;
#pragma unroll
    for (int j = 0; j < 4; j++)
        out[obase + (size_t)j * E] = acc[j];
}

// ---------------- layernorm (fp32 in, fp16 out) ------------------------
__global__ void ln_kernel(const float* __restrict__ in,
                          const float* __restrict__ g,
                          const float* __restrict__ b,
                          __half* __restrict__ out) {
    int row = blockIdx.x;
    int t = threadIdx.x;
    float v = in[(size_t)row * E + t];
    __shared__ float red[2];
    blk_reduce2(v, v * v, red, t);
    float m = red[0] * (1.0f / E);
    float var = red[1] * (1.0f / E) - m * m;
    float inv = rsqrtf(var + 1e-6f);
    out[(size_t)row * E + t] = __float2half((v - m) * inv * g[t] + b[t]);
}

// ---------------- fp16 tensor-core flash attention (3-stage) -------------
#define KVS 40
#define PSS 72
__global__ __launch_bounds__(128) void attn_f16_kernel(
        const __half* __restrict__ Q, const __half* __restrict__ Kt,
        const __half* __restrict__ V,
        const float* __restrict__ mask, const float* __restrict__ addend,
        __half* __restrict__ O, int Lq, int Lk, float scale) {
    __shared__ __align__(16) __half Qs[64 * KVS];
    __shared__ __align__(16) __half Ks[3][64 * KVS];
    __shared__ __align__(16) __half Vs[3][64 * KVS];
    __shared__ __align__(16) __half Ps[64 * PSS];

    int tid = threadIdx.x;
    int w = tid >> 5, lane = tid & 31;
    int lg = lane >> 2, lt = lane & 3;
    int h = blockIdx.y, b = blockIdx.z;
    int q0 = blockIdx.x * 64;
    int wm = w * 16;
    int ldrow = lane & 15;
    int ldcol = (lane >> 4) * 8;

    auto loadTile = [&](__half* dst, const __half* src) {
#pragma unroll
        for (int i = 0; i < 2; i++) {
            int id = tid + 128 * i;
            int row = id >> 2, gr = id & 3;
            cp16(dst + row * KVS + gr * 8, src + (size_t)row * E + gr * 8);
        }
    };
    auto loadKV = [&](int s, int j0) {
        loadTile(Ks[s], Kt + ((size_t)(b * Lk + j0)) * E + h * KD);
        loadTile(Vs[s], V  + ((size_t)(b * Lk + j0)) * E + h * KD);
        CP_COMMIT();
    };

    loadTile(Qs, Q + ((size_t)(b * Lq + q0)) * E + h * KD);
    CP_COMMIT();
    loadKV(0, 0);
    int NJ = Lk >> 6;
    if (NJ > 1) loadKV(1, 64);
    CP_WAIT(2);          // Q tile done
    __syncthreads();

    uint32_t qf[2][4];
#pragma unroll
    for (int ks = 0; ks < 2; ks++)
        LDSM_X4(qf[ks][0], qf[ks][1], qf[ks][2], qf[ks][3],
                saddr(&Qs[(wm + ldrow) * KVS + ks * 16 + ldcol]));

    float m0 = -INFINITY, m1 = -INFINITY, l0 = 0.f, l1 = 0.f;
    float oacc[4][4] = {};
    const float* mbase = mask ? (mask + ((size_t)h * Lk + q0) * Lk) : nullptr;

    for (int jt = 0; jt < NJ; jt++) {
        int j0 = jt << 6;
        if (jt + 1 < NJ) { CP_WAIT(1); } else { CP_WAIT(0); }
        __syncthreads();
        int s = jt % 3;

        float2 mv[8][2];
        if (mbase) {
            int r0 = wm + lg, r1 = wm + 8 + lg;
#pragma unroll
            for (int ni = 0; ni < 8; ni++) {
                int c = j0 + ni * 8 + lt * 2;
                mv[ni][0] = *(const float2*)&mbase[(size_t)r0 * Lk + c];
                mv[ni][1] = *(const float2*)&mbase[(size_t)r1 * Lk + c];
            }
        }

        float sacc[8][4];
#pragma unroll
        for (int ni = 0; ni < 8; ni++)
#pragma unroll
            for (int c = 0; c < 4; c++) sacc[ni][c] = 0.f;
#pragma unroll
        for (int ks = 0; ks < 2; ks++) {
#pragma unroll
            for (int nb = 0; nb < 4; nb++) {
                uint32_t r0, r1, r2, r3;
                LDSM_X4(r0, r1, r2, r3,
                        saddr(&Ks[s][(nb * 16 + ldrow) * KVS + ks * 16 + ldcol]));
                MMA_F16(sacc[2 * nb],     qf[ks][0], qf[ks][1], qf[ks][2], qf[ks][3], r0, r2);
                MMA_F16(sacc[2 * nb + 1], qf[ks][0], qf[ks][1], qf[ks][2], qf[ks][3], r1, r3);
            }
        }

        if (mbase) {
#pragma unroll
            for (int ni = 0; ni < 8; ni++) {
                sacc[ni][0] = sacc[ni][0] * scale + mv[ni][0].x;
                sacc[ni][1] = sacc[ni][1] * scale + mv[ni][0].y;
                sacc[ni][2] = sacc[ni][2] * scale + mv[ni][1].x;
                sacc[ni][3] = sacc[ni][3] * scale + mv[ni][1].y;
            }
        } else if (scale != 1.f) {
#pragma unroll
            for (int ni = 0; ni < 8; ni++)
#pragma unroll
                for (int c = 0; c < 4; c++) sacc[ni][c] *= scale;
        }

        float rm0 = -INFINITY, rm1 = -INFINITY;
#pragma unroll
        for (int ni = 0; ni < 8; ni++) {
            rm0 = fmaxf(rm0, fmaxf(sacc[ni][0], sacc[ni][1]));
            rm1 = fmaxf(rm1, fmaxf(sacc[ni][2], sacc[ni][3]));
        }
        rm0 = fmaxf(rm0, __shfl_xor_sync(0xffffffff, rm0, 1));
        rm0 = fmaxf(rm0, __shfl_xor_sync(0xffffffff, rm0, 2));
        rm1 = fmaxf(rm1, __shfl_xor_sync(0xffffffff, rm1, 1));
        rm1 = fmaxf(rm1, __shfl_xor_sync(0xffffffff, rm1, 2));
        float mn0 = fmaxf(m0, rm0), mn1 = fmaxf(m1, rm1);
        float al0 = exp2f((m0 - mn0) * LOG2E);
        float al1 = exp2f((m1 - mn1) * LOG2E);
        float rs0 = 0.f, rs1 = 0.f;
#pragma unroll
        for (int ni = 0; ni < 8; ni++) {
            float p0 = exp2f((sacc[ni][0] - mn0) * LOG2E);
            float p1 = exp2f((sacc[ni][1] - mn0) * LOG2E);
            float p2 = exp2f((sacc[ni][2] - mn1) * LOG2E);
            float p3 = exp2f((sacc[ni][3] - mn1) * LOG2E);
            rs0 += p0 + p1; rs1 += p2 + p3;
            int c = ni * 8 + lt * 2;
            *(__half2*)&Ps[(wm + lg) * PSS + c]     = __floats2half2_rn(p0, p1);
            *(__half2*)&Ps[(wm + 8 + lg) * PSS + c] = __floats2half2_rn(p2, p3);
        }
        rs0 += __shfl_xor_sync(0xffffffff, rs0, 1);
        rs0 += __shfl_xor_sync(0xffffffff, rs0, 2);
        rs1 += __shfl_xor_sync(0xffffffff, rs1, 1);
        rs1 += __shfl_xor_sync(0xffffffff, rs1, 2);
        l0 = l0 * al0 + rs0;
        l1 = l1 * al1 + rs1;
        m0 = mn0; m1 = mn1;
#pragma unroll
        for (int ni = 0; ni < 4; ni++) {
            oacc[ni][0] *= al0; oacc[ni][1] *= al0;
            oacc[ni][2] *= al1; oacc[ni][3] *= al1;
        }
        __syncwarp();

#pragma unroll
        for (int ks = 0; ks < 4; ks++) {
            uint32_t pa0, pa1, pa2, pa3;
            LDSM_X4(pa0, pa1, pa2, pa3,
                    saddr(&Ps[(wm + ldrow) * PSS + ks * 16 + ldcol]));
            uint32_t v0, v1, v2, v3;
            LDSM_X4T(v0, v1, v2, v3,
                     saddr(&Vs[s][(ks * 16 + ldrow) * KVS + 0 + ldcol]));
            uint32_t u0, u1, u2, u3;
            LDSM_X4T(u0, u1, u2, u3,
                     saddr(&Vs[s][(ks * 16 + ldrow) * KVS + 16 + ldcol]));
            MMA_F16(oacc[0], pa0, pa1, pa2, pa3, v0, v1);
            MMA_F16(oacc[1], pa0, pa1, pa2, pa3, v2, v3);
            MMA_F16(oacc[2], pa0, pa1, pa2, pa3, u0, u1);
            MMA_F16(oacc[3], pa0, pa1, pa2, pa3, u2, u3);
        }
        if (jt + 2 < NJ) loadKV((jt + 2) % 3, (jt + 2) << 6);
    }

    float inv0 = 1.f / l0, inv1 = 1.f / l1;
    int r0 = q0 + wm + lg, r1 = r0 + 8;
#pragma unroll
    for (int ni = 0; ni < 4; ni++) {
        int c = h * KD + ni * 8 + lt * 2;
        float v00 = oacc[ni][0] * inv0, v01 = oacc[ni][1] * inv0;
        float v10 = oacc[ni][2] * inv1, v11 = oacc[ni][3] * inv1;
        if (addend) {
            float2 a0 = *(const float2*)&addend[((size_t)(b * Lq + r0)) * E + c];
            float2 a1 = *(const float2*)&addend[((size_t)(b * Lq + r1)) * E + c];
            v00 += a0.x; v01 += a0.y; v10 += a1.x; v11 += a1.y;
        }
        *(__half2*)&O[((size_t)(b * Lq + r0)) * E + c] = __floats2half2_rn(v00, v01);
        *(__half2*)&O[((size_t)(b * Lq + r1)) * E + c] = __floats2half2_rn(v10, v11);
    }
}

// ---------------- launcher ----------------------------------------------
extern "C" void kernel_launch(void* const* d_in, const int* in_sizes, int n_in,
                              void* d_out, int out_size) {
    const float* x       = (const float*)d_in[0];
    const float* queries = (const float*)d_in[1];
    const float* sn      = (const float*)d_in[2];
    const float* cs      = (const float*)d_in[3];
    const float* mask    = (const float*)d_in[4];
    const float* ln1_g   = (const float*)d_in[5];
    const float* ln1_b   = (const float*)d_in[6];
    const float* ln2_g   = (const float*)d_in[7];
    const float* ln2_b   = (const float*)d_in[8];
    const float* wq      = (const float*)d_in[9];
    const float* bq      = (const float*)d_in[10];
    const float* wk      = (const float*)d_in[11];
    const float* bk      = (const float*)d_in[12];
    const float* wv      = (const float*)d_in[13];
    const float* bv      = (const float*)d_in[14];
    const float* lepe_w  = (const float*)d_in[15];
    const float* lepe_b  = (const float*)d_in[16];
    const float* wo      = (const float*)d_in[17];
    const float* bo      = (const float*)d_in[18];
    const float* fc1_w   = (const float*)d_in[19];
    const float* fc1_b   = (const float*)d_in[20];
    const float* fc2_w   = (const float*)d_in[21];
    const float* fc2_b   = (const float*)d_in[22];
    const float* pos_w   = (const float*)d_in[23];
    const float* pos_b   = (const float*)d_in[24];
    const float* ca_in_w = (const float*)d_in[25];
    const float* ca_in_b = (const float*)d_in[26];
    const float* ca_out_w= (const float*)d_in[27];
    const float* ca_out_b= (const float*)d_in[28];

    void* sp = nullptr;
    cudaGetSymbolAddress(&sp, g_scratch);
    float* S = (float*)sp;
    float* X1   = S + OFF_X1;
    float* LEPE = S + OFF_LEPE;
    float* X2   = S + OFF_X2;
    float* Q2   = S + OFF_Q2;
    __half* HN   = (__half*)(S + OFF_HN);
    __half* QH   = (__half*)(S + OFF_QH);
    __half* KH   = (__half*)(S + OFF_KH);
    __half* VH   = (__half*)(S + OFF_VH);
    __half* AOH  = (__half*)(S + OFF_AOH);
    __half* XH   = (__half*)(S + OFF_XH);
    __half* CKH  = (__half*)(S + OFF_CKH);
    __half* CVH  = (__half*)(S + OFF_CVH);
    __half* FF   = (__half*)(S + OFF_FF);
    __half* CQH  = (__half*)(S + OFF_CQH);
    __half* CAOH = (__half*)(S + OFF_CAOH);
    __half* QLN  = (__half*)(S + OFF_QLN);
    __half* QLN2 = (__half*)(S + OFF_QLN2);
    __half* QFF  = (__half*)(S + OFF_QFF);
    __half* WHb  = (__half*)(S + OFF_WH);

    float* OX = (float*)d_out;
    float* OQ = OX + (size_t)Bb * L * E;

    const int MTOK = Bb * L;   // 8192
    const int MQ   = Bb * NQ;  // 512
    dim3 sp3(WW, HH, Bb);
    dim3 c5(WW / 4, HH, Bb);

    // 0. weights -> fp16
    wconv_kernel<<<dim3(128, 8), 256>>>(wq, wk, wv, wo, fc1_w, fc2_w,
                                        ca_in_w, ca_out_w, WHb);
    // 1. x1 = x + dwconv3(x); hn = LN1(x1) fp16
    dwconv3_ln_kernel<<<sp3, 256>>>(x, pos_w, pos_b, ln1_g, ln1_b, X1, HN);
    // 2. q(theta), k(theta,*scaling), v(fp16)
    qkv_gemm_kernel<<<dim3(E/64, MTOK/128, 3), 256>>>(
        HN, WHb, bq, bk, bv, QH, KH, VH, sn, cs);
    // 3. lepe = dwconv5(v)
    dwconv5_kernel<<<c5, 256>>>(VH, lepe_w, lepe_b, LEPE);
    // 4. self attention + lepe -> AOH fp16
    attn_f16_kernel<<<dim3(L/64, HEADS, Bb), 128>>>(
        QH, KH, VH, mask, LEPE, AOH, L, L, 1.f);
    // 5. x2 = x1 + aoh @ wo^T + bo
    gemm_kernel<<<dim3(E/64, MTOK/128), 256>>>(AOH, WHb + WH_WO, bo, X1, X2, nullptr, MTOK, E, E, 1.f, EPI_NONE);
    // 6. FFN on x
    ln_kernel<<<MTOK, 256>>>(X2, ln2_g, ln2_b, HN);
    gemm_kernel<<<dim3(FFN/64, MTOK/128), 256>>>(HN, WHb + WH_FC1, fc1_b, nullptr, nullptr, FF, MTOK, FFN, E, 1.f, EPI_GELU);
    gemm_kernel<<<dim3(E/64, MTOK/128), 256>>>(FF, WHb + WH_FC2, fc2_b, X2, OX, XH, MTOK, E, FFN, 1.f, EPI_NONE);
    // 7. cross attention
    ln_kernel<<<MQ, 256>>>(queries, ln1_g, ln1_b, QLN);
    gemm_kernel<<<dim3(E/64, MQ/128), 256>>>(QLN, WHb + WH_CAIN, ca_in_b, nullptr, nullptr, CQH, MQ, E, E, 1.f, EPI_NONE);
    ckv_gemm_kernel<<<dim3(E/64, MTOK/128, 2), 256>>>(XH, WHb, ca_in_b, CKH, CVH);
    attn_f16_kernel<<<dim3(NQ/64, HEADS, Bb), 128>>>(
        CQH, CKH, CVH, nullptr, nullptr, CAOH, NQ, L, SCALING);
    gemm_kernel<<<dim3(E/64, MQ/128), 256>>>(CAOH, WHb + WH_CAOUT, ca_out_b, queries, Q2, nullptr, MQ, E, E, 1.f, EPI_NONE);
    // 8. FFN on queries
    ln_kernel<<<MQ, 256>>>(Q2, ln2_g, ln2_b, QLN2);
    gemm_kernel<<<dim3(FFN/64, MQ/128), 256>>>(QLN2, WHb + WH_FC1, fc1_b, nullptr, nullptr, QFF, MQ, FFN, E, 1.f, EPI_GELU);
    gemm_kernel<<<dim3(E/64, MQ/128), 256>>>(QFF, WHb + WH_FC2, fc2_b, Q2, OQ, nullptr, MQ, E, FFN, 1.f, EPI_NONE);
}